// round 1
// baseline (speedup 1.0000x reference)
#include <cuda_runtime.h>
#include <math.h>

// ---------------------------------------------------------------------------
// Problem constants (fixed shapes from reference)
// ---------------------------------------------------------------------------
#define NB     2
#define SEQ    2048
#define T_TOK  4096          // NB*SEQ
#define DMODEL 1024
#define NH     16
#define HD     64
#define WINDOW 1024
#define NE     8
#define DFF    2048
#define CAP    512           // int(1.0 * T / E)
#define OUT_MAIN (T_TOK * DMODEL)

// ---------------------------------------------------------------------------
// Scratch (static device globals -- allocation-free kernel_launch)
// ---------------------------------------------------------------------------
__device__ float g_xn  [T_TOK * DMODEL];
__device__ float g_q   [T_TOK * DMODEL];
__device__ float g_k   [T_TOK * DMODEL];
__device__ float g_v   [T_TOK * DMODEL];
__device__ float g_ao  [T_TOK * DMODEL];
__device__ float g_h   [T_TOK * DMODEL];
__device__ float g_xn2 [T_TOK * DMODEL];
__device__ float g_wte [T_TOK * NE];
__device__ float g_hid [NE * CAP * 2 * DFF];   // 64 MB
__device__ float g_act [NE * CAP * DFF];       // 32 MB
__device__ int   g_capidx[NE * CAP];
__device__ float g_capval[NE * CAP];
__device__ float g_phis[NE];

// ---------------------------------------------------------------------------
// RMSNorm: one block per row (D=1024), 256 threads
// ---------------------------------------------------------------------------
__global__ void rmsnorm_kernel(const float* __restrict__ x,
                               const float* __restrict__ w,
                               float* __restrict__ o)
{
    int row = blockIdx.x;
    const float* xr = x + (long long)row * DMODEL;
    float vals[4];
    float ss = 0.f;
#pragma unroll
    for (int t = 0; t < 4; t++) {
        float v = xr[threadIdx.x + t * 256];
        vals[t] = v;
        ss += v * v;
    }
    __shared__ float red[8];
#pragma unroll
    for (int off = 16; off; off >>= 1)
        ss += __shfl_xor_sync(0xffffffffu, ss, off);
    if ((threadIdx.x & 31) == 0) red[threadIdx.x >> 5] = ss;
    __syncthreads();
    if (threadIdx.x == 0) {
        float s = 0.f;
#pragma unroll
        for (int i = 0; i < 8; i++) s += red[i];
        red[0] = s;
    }
    __syncthreads();
    float rinv = 1.f / sqrtf(red[0] / (float)DMODEL + 1e-6f);
    float* orow = o + (long long)row * DMODEL;
#pragma unroll
    for (int t = 0; t < 4; t++) {
        int d = threadIdx.x + t * 256;
        orow[d] = vals[t] * rinv * w[d];
    }
}

// ---------------------------------------------------------------------------
// Generic tiled SGEMM: C[M,N] = gather(A)[M,K] @ B[K,N] (+epilogues)
// EPI 0: plain store. EPI 1: += resid. EPI 2: scatter atomicAdd with row scale.
// blockIdx.z = batch (expert); strides in elements.
// BM=BN=64, BK=16, 256 threads, 4x4 per thread.
// ---------------------------------------------------------------------------
template<int EPI>
__global__ void sgemm_kernel(const float* __restrict__ A,
                             const float* __restrict__ B,
                             float* __restrict__ C,
                             const float* __restrict__ resid,
                             const int*  __restrict__ rowIdxA,
                             const int*  __restrict__ outIdx,
                             const float* __restrict__ rowScale,
                             int M, int N, int K,
                             long long aB, long long bB, long long cB, int idxB)
{
    int e = blockIdx.z;
    A += (long long)e * aB;
    B += (long long)e * bB;
    C += (long long)e * cB;
    if (rowIdxA)  rowIdxA  += e * idxB;
    if (outIdx)   outIdx   += e * idxB;
    if (rowScale) rowScale += e * idxB;

    __shared__ float As[16][68];   // A^T tile (padded)
    __shared__ float Bs[16][64];

    int tid = threadIdx.x;
    int tx = tid & 15, ty = tid >> 4;
    int rowBase = blockIdx.y * 64;
    int colBase = blockIdx.x * 64;

    float acc[4][4] = {};

    for (int k0 = 0; k0 < K; k0 += 16) {
#pragma unroll
        for (int i = tid; i < 64 * 16; i += 256) {
            int m = i >> 4, kk = i & 15;
            int ar = rowBase + m;
            int arow = rowIdxA ? rowIdxA[ar] : ar;
            As[kk][m] = A[(long long)arow * K + k0 + kk];
        }
#pragma unroll
        for (int i = tid; i < 16 * 64; i += 256) {
            int kk = i >> 6, n = i & 63;
            Bs[kk][n] = B[(long long)(k0 + kk) * N + colBase + n];
        }
        __syncthreads();
#pragma unroll
        for (int kk = 0; kk < 16; kk++) {
            float a[4], b[4];
#pragma unroll
            for (int i = 0; i < 4; i++) a[i] = As[kk][ty * 4 + i];
#pragma unroll
            for (int j = 0; j < 4; j++) b[j] = Bs[kk][tx * 4 + j];
#pragma unroll
            for (int i = 0; i < 4; i++)
#pragma unroll
                for (int j = 0; j < 4; j++)
                    acc[i][j] = fmaf(a[i], b[j], acc[i][j]);
        }
        __syncthreads();
    }

#pragma unroll
    for (int i = 0; i < 4; i++) {
        int m = rowBase + ty * 4 + i;
#pragma unroll
        for (int j = 0; j < 4; j++) {
            int n = colBase + tx * 4 + j;
            float v = acc[i][j];
            if (EPI == 1) {
                v += resid[(long long)m * N + n];
                C[(long long)m * N + n] = v;
            } else if (EPI == 2) {
                atomicAdd(&C[(long long)outIdx[m] * N + n], v * rowScale[m]);
            } else {
                C[(long long)m * N + n] = v;
            }
        }
    }
}

// ---------------------------------------------------------------------------
// RoPE (in-place on q and k). One thread per (token,head,freq-pair).
// ---------------------------------------------------------------------------
__global__ void rope_kernel(float* __restrict__ q, float* __restrict__ k)
{
    int idx = blockIdx.x * blockDim.x + threadIdx.x;
    if (idx >= T_TOK * NH * (HD / 2)) return;
    int j   = idx & 31;
    int hh  = (idx >> 5) & 15;
    int row = idx >> 9;
    int s   = row & (SEQ - 1);

    float inv = (float)(1.0 / pow(10000.0, (double)j / 32.0));
    float ang = (float)s * inv;
    float c = cosf(ang), sn = sinf(ang);

    long long base = (long long)row * DMODEL + hh * HD;
    float q1 = q[base + j], q2 = q[base + j + 32];
    q[base + j]      = q1 * c - q2 * sn;
    q[base + j + 32] = q2 * c + q1 * sn;
    float k1 = k[base + j], k2 = k[base + j + 32];
    k[base + j]      = k1 * c - k2 * sn;
    k[base + j + 32] = k2 * c + k1 * sn;
}

// ---------------------------------------------------------------------------
// Sliding-window attention, online softmax.
// grid (qtiles=32, H=16, B=2), 256 threads, dyn smem 49408B.
// ---------------------------------------------------------------------------
__global__ void attn_kernel(const float* __restrict__ q,
                            const float* __restrict__ k,
                            const float* __restrict__ v,
                            float* __restrict__ o)
{
    extern __shared__ float sm[];
    float* Qs = sm;                         // [64][64]
    float* KP = sm + 64 * 64;               // [64][65]  K^T, then P
    float* Vs = sm + 64 * 64 + 64 * 65;     // [64][64]

    int qt = blockIdx.x, h = blockIdx.y, b = blockIdx.z;
    int i0 = qt * 64;
    int tid = threadIdx.x, tx = tid & 15, ty = tid >> 4;
    long long base = ((long long)b * SEQ) * DMODEL + h * HD;

    for (int i = tid; i < 4096; i += 256) {
        int r = i >> 6, d = i & 63;
        Qs[r * 64 + d] = q[base + (long long)(i0 + r) * DMODEL + d] * 0.125f;
    }

    float m_i[4], l_i[4], accO[4][4];
#pragma unroll
    for (int i = 0; i < 4; i++) {
        m_i[i] = -1e30f; l_i[i] = 0.f;
#pragma unroll
        for (int j = 0; j < 4; j++) accO[i][j] = 0.f;
    }

    int jstart = i0 - (WINDOW - 1); if (jstart < 0) jstart = 0;
    int jt0 = jstart >> 6;
    int jt1 = (i0 + 63) >> 6;

    for (int jt = jt0; jt <= jt1; jt++) {
        int j0 = jt << 6;
        for (int i = tid; i < 4096; i += 256) {
            int jj = i >> 6, d = i & 63;
            long long g = base + (long long)(j0 + jj) * DMODEL + d;
            KP[d * 65 + jj] = k[g];
            Vs[jj * 64 + d] = v[g];
        }
        __syncthreads();

        // S = Qs @ K^T
        float s[4][4] = {};
#pragma unroll 8
        for (int kk = 0; kk < 64; kk++) {
            float a[4], bb[4];
#pragma unroll
            for (int i = 0; i < 4; i++) a[i] = Qs[(ty * 4 + i) * 64 + kk];
#pragma unroll
            for (int j = 0; j < 4; j++) bb[j] = KP[kk * 65 + tx * 4 + j];
#pragma unroll
            for (int i = 0; i < 4; i++)
#pragma unroll
                for (int j = 0; j < 4; j++)
                    s[i][j] = fmaf(a[i], bb[j], s[i][j]);
        }

        // mask + row max
        float tmax[4];
#pragma unroll
        for (int i = 0; i < 4; i++) {
            int ii = i0 + ty * 4 + i;
            float mx = -1e30f;
#pragma unroll
            for (int j = 0; j < 4; j++) {
                int jj = j0 + tx * 4 + j;
                int diff = ii - jj;
                if (diff < 0 || diff >= WINDOW) s[i][j] = -1e30f;
                mx = fmaxf(mx, s[i][j]);
            }
            tmax[i] = mx;
        }
#pragma unroll
        for (int off = 1; off < 16; off <<= 1)
#pragma unroll
            for (int i = 0; i < 4; i++)
                tmax[i] = fmaxf(tmax[i], __shfl_xor_sync(0xffffffffu, tmax[i], off));

        float alpha[4], rsum[4];
#pragma unroll
        for (int i = 0; i < 4; i++) {
            float mnew = fmaxf(m_i[i], tmax[i]);
            alpha[i] = expf(m_i[i] - mnew);
            m_i[i] = mnew;
            rsum[i] = 0.f;
            int ii = i0 + ty * 4 + i;
#pragma unroll
            for (int j = 0; j < 4; j++) {
                int jj = j0 + tx * 4 + j;
                int diff = ii - jj;
                float p = (diff < 0 || diff >= WINDOW) ? 0.f : expf(s[i][j] - mnew);
                s[i][j] = p;        // reuse as P
                rsum[i] += p;
            }
        }
#pragma unroll
        for (int off = 1; off < 16; off <<= 1)
#pragma unroll
            for (int i = 0; i < 4; i++)
                rsum[i] += __shfl_xor_sync(0xffffffffu, rsum[i], off);
#pragma unroll
        for (int i = 0; i < 4; i++) {
            l_i[i] = l_i[i] * alpha[i] + rsum[i];
#pragma unroll
            for (int j = 0; j < 4; j++) accO[i][j] *= alpha[i];
        }

        __syncthreads();                       // done reading K
#pragma unroll
        for (int i = 0; i < 4; i++)
#pragma unroll
            for (int j = 0; j < 4; j++)
                KP[(ty * 4 + i) * 65 + tx * 4 + j] = s[i][j];
        __syncthreads();

        // O += P @ V
#pragma unroll 8
        for (int kk = 0; kk < 64; kk++) {
            float a[4], bb[4];
#pragma unroll
            for (int i = 0; i < 4; i++) a[i] = KP[(ty * 4 + i) * 65 + kk];
#pragma unroll
            for (int j = 0; j < 4; j++) bb[j] = Vs[kk * 64 + tx * 4 + j];
#pragma unroll
            for (int i = 0; i < 4; i++)
#pragma unroll
                for (int j = 0; j < 4; j++)
                    accO[i][j] = fmaf(a[i], bb[j], accO[i][j]);
        }
        __syncthreads();
    }

#pragma unroll
    for (int i = 0; i < 4; i++) {
        int r = i0 + ty * 4 + i;
        float rl = 1.f / l_i[i];
#pragma unroll
        for (int j = 0; j < 4; j++)
            o[base + (long long)r * DMODEL + tx * 4 + j] = accO[i][j] * rl;
    }
}

// ---------------------------------------------------------------------------
// Gating: one warp per token. probs, top-2 (ties -> lower index), phi sums.
// ---------------------------------------------------------------------------
__global__ void gate_kernel(const float* __restrict__ xn2,
                            const float* __restrict__ gw,
                            float* __restrict__ wte,
                            float* __restrict__ phis)
{
    int tok  = (blockIdx.x * blockDim.x + threadIdx.x) >> 5;
    int lane = threadIdx.x & 31;
    if (tok >= T_TOK) return;
    const float* xr = xn2 + (long long)tok * DMODEL;
    float acc[NE];
#pragma unroll
    for (int e = 0; e < NE; e++) acc[e] = 0.f;
    for (int d = lane; d < DMODEL; d += 32) {
        float xv = xr[d];
        const float* g = gw + d * NE;
#pragma unroll
        for (int e = 0; e < NE; e++) acc[e] = fmaf(xv, g[e], acc[e]);
    }
#pragma unroll
    for (int e = 0; e < NE; e++)
#pragma unroll
        for (int off = 16; off; off >>= 1)
            acc[e] += __shfl_xor_sync(0xffffffffu, acc[e], off);

    if (lane == 0) {
        float mx = acc[0];
#pragma unroll
        for (int e = 1; e < NE; e++) mx = fmaxf(mx, acc[e]);
        float p[NE], s = 0.f;
#pragma unroll
        for (int e = 0; e < NE; e++) { p[e] = expf(acc[e] - mx); s += p[e]; }
#pragma unroll
        for (int e = 0; e < NE; e++) p[e] /= s;
        int i1 = 0;
#pragma unroll
        for (int e = 1; e < NE; e++) if (p[e] > p[i1]) i1 = e;
        int i2 = -1;
#pragma unroll
        for (int e = 0; e < NE; e++)
            if (e != i1 && (i2 < 0 || p[e] > p[i2])) i2 = e;
#pragma unroll
        for (int e = 0; e < NE; e++)
            wte[(long long)tok * NE + e] = (e == i1) ? p[i1] : (e == i2) ? p[i2] : 0.f;
#pragma unroll
        for (int e = 0; e < NE; e++) atomicAdd(&phis[e], p[e]);
    }
}

// ---------------------------------------------------------------------------
// Per-expert top-CAP selection via bitonic sort (stable: ties -> lower index).
// one block per expert, 1024 threads, 32KB smem.
// ---------------------------------------------------------------------------
__global__ void expert_topk_kernel(const float* __restrict__ wte,
                                   int* __restrict__ capidx,
                                   float* __restrict__ capval)
{
    __shared__ float sv[T_TOK];
    __shared__ int   si[T_TOK];
    int e = blockIdx.x;
    for (int i = threadIdx.x; i < T_TOK; i += 1024) {
        sv[i] = wte[(long long)i * NE + e];
        si[i] = i;
    }
    __syncthreads();
    for (int kk = 2; kk <= T_TOK; kk <<= 1) {
        for (int j = kk >> 1; j > 0; j >>= 1) {
            for (int i = threadIdx.x; i < T_TOK; i += 1024) {
                int l = i ^ j;
                if (l > i) {
                    bool dir = ((i & kk) == 0);   // want "before"-ordered (descending)
                    float vi = sv[i], vl = sv[l];
                    int   xi = si[i], xl = si[l];
                    bool before = (vi > vl) || (vi == vl && xi < xl);
                    if (before != dir) {
                        sv[i] = vl; sv[l] = vi;
                        si[i] = xl; si[l] = xi;
                    }
                }
            }
            __syncthreads();
        }
    }
    for (int i = threadIdx.x; i < CAP; i += 1024) {
        capidx[e * CAP + i] = si[i];
        capval[e * CAP + i] = sv[i];
    }
}

// ---------------------------------------------------------------------------
// SwiGLU activation: act = h1 * silu(h2)
// ---------------------------------------------------------------------------
__global__ void act_kernel(const float* __restrict__ hid, float* __restrict__ act)
{
    long long idx = (long long)blockIdx.x * blockDim.x + threadIdx.x;
    if (idx >= (long long)NE * CAP * DFF) return;
    int f = (int)(idx % DFF);
    long long row = idx / DFF;                  // e*CAP + c
    long long hbase = row * (2 * DFF);
    float h1 = hid[hbase + f];
    float h2 = hid[hbase + DFF + f];
    act[idx] = h1 * (h2 / (1.f + expf(-h2)));
}

// ---------------------------------------------------------------------------
// Small utility kernels
// ---------------------------------------------------------------------------
__global__ void zero_phis_kernel(float* __restrict__ phis)
{
    if (threadIdx.x < NE) phis[threadIdx.x] = 0.f;
}

__global__ void copy_kernel(const float* __restrict__ src, float* __restrict__ dst)
{
    long long idx = (long long)blockIdx.x * blockDim.x + threadIdx.x;
    if (idx < (long long)OUT_MAIN) dst[idx] = src[idx];
}

__global__ void aux_kernel(const float* __restrict__ phis, float* __restrict__ out, int out_size)
{
    if (out_size > OUT_MAIN) {
        float s = 0.f;
#pragma unroll
        for (int e = 0; e < NE; e++) {
            float pm = phis[e] / (float)T_TOK;
            s += pm * pm;
        }
        out[OUT_MAIN] = (float)NE * s;
    }
}

// ---------------------------------------------------------------------------
// Launch
// ---------------------------------------------------------------------------
extern "C" void kernel_launch(void* const* d_in, const int* in_sizes, int n_in,
                              void* d_out, int out_size)
{
    const float* x   = (const float*)d_in[0];
    const float* wq  = (const float*)d_in[1];
    const float* wk  = (const float*)d_in[2];
    const float* wv  = (const float*)d_in[3];
    const float* wo  = (const float*)d_in[4];
    const float* n1w = (const float*)d_in[5];
    const float* n2w = (const float*)d_in[6];
    const float* gw  = (const float*)d_in[7];
    const float* w1  = (const float*)d_in[8];
    const float* w2  = (const float*)d_in[9];
    float* out = (float*)d_out;

    float *xn, *qb, *kb, *vb, *ao, *hb, *xn2, *wte, *hid, *act, *capv, *phis;
    int* capi;
    cudaGetSymbolAddress((void**)&xn,  g_xn);
    cudaGetSymbolAddress((void**)&qb,  g_q);
    cudaGetSymbolAddress((void**)&kb,  g_k);
    cudaGetSymbolAddress((void**)&vb,  g_v);
    cudaGetSymbolAddress((void**)&ao,  g_ao);
    cudaGetSymbolAddress((void**)&hb,  g_h);
    cudaGetSymbolAddress((void**)&xn2, g_xn2);
    cudaGetSymbolAddress((void**)&wte, g_wte);
    cudaGetSymbolAddress((void**)&hid, g_hid);
    cudaGetSymbolAddress((void**)&act, g_act);
    cudaGetSymbolAddress((void**)&capi, g_capidx);
    cudaGetSymbolAddress((void**)&capv, g_capval);
    cudaGetSymbolAddress((void**)&phis, g_phis);

    const int ATTN_SMEM = (64 * 64 + 64 * 65 + 64 * 64) * 4;   // 49408 B
    cudaFuncSetAttribute(attn_kernel, cudaFuncAttributeMaxDynamicSharedMemorySize, ATTN_SMEM);

    // ---- sublayer 1 ----
    rmsnorm_kernel<<<T_TOK, 256>>>(x, n1w, xn);

    dim3 gProj(DMODEL / 64, T_TOK / 64, 1);
    sgemm_kernel<0><<<gProj, 256>>>(xn, wq, qb, nullptr, nullptr, nullptr, nullptr,
                                    T_TOK, DMODEL, DMODEL, 0, 0, 0, 0);
    sgemm_kernel<0><<<gProj, 256>>>(xn, wk, kb, nullptr, nullptr, nullptr, nullptr,
                                    T_TOK, DMODEL, DMODEL, 0, 0, 0, 0);
    sgemm_kernel<0><<<gProj, 256>>>(xn, wv, vb, nullptr, nullptr, nullptr, nullptr,
                                    T_TOK, DMODEL, DMODEL, 0, 0, 0, 0);

    rope_kernel<<<(T_TOK * NH * 32 + 255) / 256, 256>>>(qb, kb);

    attn_kernel<<<dim3(SEQ / 64, NH, NB), 256, ATTN_SMEM>>>(qb, kb, vb, ao);

    sgemm_kernel<1><<<gProj, 256>>>(ao, wo, hb, x, nullptr, nullptr, nullptr,
                                    T_TOK, DMODEL, DMODEL, 0, 0, 0, 0);

    // ---- sublayer 2: MoE ----
    rmsnorm_kernel<<<T_TOK, 256>>>(hb, n2w, xn2);

    zero_phis_kernel<<<1, 32>>>(phis);
    gate_kernel<<<(T_TOK * 32) / 256, 256>>>(xn2, gw, wte, phis);
    expert_topk_kernel<<<NE, 1024>>>(wte, capi, capv);

    // hidden[e] = xn2[capidx[e]] @ w1[e]   (M=512, K=1024, N=4096)
    sgemm_kernel<0><<<dim3((2 * DFF) / 64, CAP / 64, NE), 256>>>(
        xn2, w1, hid, nullptr, capi, nullptr, nullptr,
        CAP, 2 * DFF, DMODEL,
        0, (long long)DMODEL * 2 * DFF, (long long)CAP * 2 * DFF, CAP);

    act_kernel<<<(NE * CAP * DFF + 255) / 256, 256>>>(hid, act);

    copy_kernel<<<(OUT_MAIN + 255) / 256, 256>>>(hb, out);

    // out[capidx[e][c]] += (act[e] @ w2[e])[c] * capval[e][c]  (M=512,K=2048,N=1024)
    sgemm_kernel<2><<<dim3(DMODEL / 64, CAP / 64, NE), 256>>>(
        act, w2, out, nullptr, nullptr, capi, capv,
        CAP, DMODEL, DFF,
        (long long)CAP * DFF, (long long)DFF * DMODEL, 0, CAP);

    aux_kernel<<<1, 1>>>(phis, out, out_size);

    (void)in_sizes; (void)n_in;
}

// round 4
// speedup vs baseline: 2.3606x; 2.3606x over previous
#include <cuda_runtime.h>
#include <cstdint>
#include <math.h>
#include <mma.h>

using namespace nvcuda;

// ---------------------------------------------------------------------------
// Problem constants
// ---------------------------------------------------------------------------
#define NB     2
#define SEQ    2048
#define T_TOK  4096
#define DMODEL 1024
#define NH     16
#define HD     64
#define WINDOW 1024
#define NE     8
#define DFF    2048
#define CAP    512
#define OUT_MAIN (T_TOK * DMODEL)

// ---------------------------------------------------------------------------
// Scratch
// ---------------------------------------------------------------------------
__device__ float g_xn  [T_TOK * DMODEL];
__device__ float g_q   [T_TOK * DMODEL];
__device__ float g_k   [T_TOK * DMODEL];
__device__ float g_v   [T_TOK * DMODEL];
__device__ float g_ao  [T_TOK * DMODEL];
__device__ float g_h   [T_TOK * DMODEL];
__device__ float g_xn2 [T_TOK * DMODEL];
__device__ float g_wte [T_TOK * NE];
__device__ float g_hid [NE * CAP * 2 * DFF];
__device__ float g_act [NE * CAP * DFF];
__device__ int   g_capidx[NE * CAP];
__device__ float g_capval[NE * CAP];
__device__ float g_phis[NE];

// ---------------------------------------------------------------------------
// cp.async helpers
// ---------------------------------------------------------------------------
__device__ __forceinline__ void cp16(void* dst, const void* src)
{
    unsigned int d = (unsigned int)__cvta_generic_to_shared(dst);
    asm volatile("cp.async.cg.shared.global [%0], [%1], 16;\n" :: "r"(d), "l"(src));
}
__device__ __forceinline__ void cp_commit() { asm volatile("cp.async.commit_group;\n"); }
__device__ __forceinline__ void cp_wait1()  { asm volatile("cp.async.wait_group 1;\n"); }
__device__ __forceinline__ void cp_wait0()  { asm volatile("cp.async.wait_group 0;\n"); }

// ---------------------------------------------------------------------------
// RMSNorm
// ---------------------------------------------------------------------------
__global__ void rmsnorm_kernel(const float* __restrict__ x,
                               const float* __restrict__ w,
                               float* __restrict__ o)
{
    int row = blockIdx.x;
    const float* xr = x + (long long)row * DMODEL;
    float vals[4];
    float ss = 0.f;
#pragma unroll
    for (int t = 0; t < 4; t++) {
        float v = xr[threadIdx.x + t * 256];
        vals[t] = v;
        ss += v * v;
    }
    __shared__ float red[8];
#pragma unroll
    for (int off = 16; off; off >>= 1)
        ss += __shfl_xor_sync(0xffffffffu, ss, off);
    if ((threadIdx.x & 31) == 0) red[threadIdx.x >> 5] = ss;
    __syncthreads();
    if (threadIdx.x == 0) {
        float s = 0.f;
#pragma unroll
        for (int i = 0; i < 8; i++) s += red[i];
        red[0] = s;
    }
    __syncthreads();
    float rinv = 1.f / sqrtf(red[0] / (float)DMODEL + 1e-6f);
    float* orow = o + (long long)row * DMODEL;
#pragma unroll
    for (int t = 0; t < 4; t++) {
        int d = threadIdx.x + t * 256;
        orow[d] = vals[t] * rinv * w[d];
    }
}

// ---------------------------------------------------------------------------
// WMMA tf32 GEMM: C[M,N] = gather(A)[M,K] @ B[K,N]
// Tile 128x128, BK=32, 256 threads (8 warps, each 32x64).
// EPI 0: plain. EPI 1: += resid. EPI 2: scatter atomicAdd * rowScale.
// ---------------------------------------------------------------------------
#define ALD 36
#define BLD 132
#define STAGE_F (128 * ALD + 32 * BLD)   // 8832 floats
#define GEMM_SMEM_BYTES (2 * STAGE_F * 4)  // 70656

template<int EPI>
__global__ __launch_bounds__(256)
void wgemm_kernel(const float* __restrict__ A,
                  const float* __restrict__ B,
                  float* __restrict__ C,
                  const float* __restrict__ resid,
                  const int*  __restrict__ rowIdxA,
                  const int*  __restrict__ outIdx,
                  const float* __restrict__ rowScale,
                  int N, int K,
                  long long aB, long long bB, long long cB, int idxB)
{
    extern __shared__ float sm[];
    __shared__ int   idx_sm[128];
    __shared__ float scl_sm[128];

    int e = blockIdx.z;
    A += (long long)e * aB;
    B += (long long)e * bB;
    C += (long long)e * cB;

    int tid = threadIdx.x;
    int w   = tid >> 5;
    int wr  = w >> 1;         // 0..3
    int wc  = w & 1;          // 0..1
    int rowBase = blockIdx.y * 128;
    int colBase = blockIdx.x * 128;

    if (tid < 128) {
        int ar = rowBase + tid;
        idx_sm[tid] = rowIdxA ? rowIdxA[e * idxB + ar] : ar;
        if (EPI == 2) {
            scl_sm[tid] = rowScale[e * idxB + ar];
            idx_sm[tid] = outIdx[e * idxB + ar];   // EPI2: scatter target rows
        }
    }
    __syncthreads();

    wmma::fragment<wmma::accumulator, 16, 16, 8, float> acc[2][4];
#pragma unroll
    for (int i = 0; i < 2; i++)
#pragma unroll
        for (int j = 0; j < 4; j++) wmma::fill_fragment(acc[i][j], 0.f);

    int nIt = K >> 5;

    // tile loader
    auto load_tile = [&](int it, int buf) {
        float* As = sm + buf * STAGE_F;
        float* Bs = As + 128 * ALD;
        int k0 = it << 5;
#pragma unroll
        for (int t = 0; t < 4; t++) {
            int g  = tid + t * 256;
            int m  = g >> 3;
            int kq = (g & 7) << 2;
            long long arow = (EPI == 2) ? (long long)(rowBase + m) : (long long)idx_sm[m];
            cp16(As + m * ALD + kq, A + arow * K + k0 + kq);
        }
#pragma unroll
        for (int t = 0; t < 4; t++) {
            int g  = tid + t * 256;
            int kk = g >> 5;
            int nq = (g & 31) << 2;
            cp16(Bs + kk * BLD + nq, B + (long long)(k0 + kk) * N + colBase + nq);
        }
        cp_commit();
    };

    load_tile(0, 0);
    for (int it = 0; it < nIt; it++) {
        if (it + 1 < nIt) { load_tile(it + 1, (it + 1) & 1); cp_wait1(); }
        else cp_wait0();
        __syncthreads();

        float* As = sm + (it & 1) * STAGE_F;
        float* Bs = As + 128 * ALD;
#pragma unroll
        for (int ks = 0; ks < 4; ks++) {
            wmma::fragment<wmma::matrix_a, 16, 16, 8, wmma::precision::tf32, wmma::row_major> a[2];
            wmma::fragment<wmma::matrix_b, 16, 16, 8, wmma::precision::tf32, wmma::row_major> b[4];
#pragma unroll
            for (int i = 0; i < 2; i++) {
                wmma::load_matrix_sync(a[i], As + (wr * 32 + i * 16) * ALD + ks * 8, ALD);
#pragma unroll
                for (int u = 0; u < a[i].num_elements; u++)
                    a[i].x[u] = wmma::__float_to_tf32(a[i].x[u]);
            }
#pragma unroll
            for (int j = 0; j < 4; j++) {
                wmma::load_matrix_sync(b[j], Bs + (ks * 8) * BLD + wc * 64 + j * 16, BLD);
#pragma unroll
                for (int u = 0; u < b[j].num_elements; u++)
                    b[j].x[u] = wmma::__float_to_tf32(b[j].x[u]);
            }
#pragma unroll
            for (int i = 0; i < 2; i++)
#pragma unroll
                for (int j = 0; j < 4; j++)
                    wmma::mma_sync(acc[i][j], a[i], b[j], acc[i][j]);
        }
        __syncthreads();
    }

    if (EPI == 0) {
#pragma unroll
        for (int i = 0; i < 2; i++)
#pragma unroll
            for (int j = 0; j < 4; j++) {
                long long m = rowBase + wr * 32 + i * 16;
                long long n = colBase + wc * 64 + j * 16;
                wmma::store_matrix_sync(C + m * N + n, acc[i][j], N, wmma::mem_row_major);
            }
    } else {
        float* Csm = sm;   // 128 x 132
#pragma unroll
        for (int i = 0; i < 2; i++)
#pragma unroll
            for (int j = 0; j < 4; j++)
                wmma::store_matrix_sync(Csm + (wr * 32 + i * 16) * BLD + wc * 64 + j * 16,
                                        acc[i][j], BLD, wmma::mem_row_major);
        __syncthreads();
        if (EPI == 1) {
#pragma unroll
            for (int t = 0; t < 64; t++) {
                int idx = tid + t * 256;
                int m = idx >> 7, n = idx & 127;
                long long gm = (long long)(rowBase + m) * N + colBase + n;
                C[gm] = Csm[m * BLD + n] + resid[gm];
            }
        } else { // EPI 2
#pragma unroll
            for (int t = 0; t < 64; t++) {
                int idx = tid + t * 256;
                int m = idx >> 7, n = idx & 127;
                atomicAdd(&C[(long long)idx_sm[m] * N + colBase + n],
                          Csm[m * BLD + n] * scl_sm[m]);
            }
        }
    }
}

// ---------------------------------------------------------------------------
// RoPE
// ---------------------------------------------------------------------------
__global__ void rope_kernel(float* __restrict__ q, float* __restrict__ k)
{
    int idx = blockIdx.x * blockDim.x + threadIdx.x;
    if (idx >= T_TOK * NH * (HD / 2)) return;
    int j   = idx & 31;
    int hh  = (idx >> 5) & 15;
    int row = idx >> 9;
    int s   = row & (SEQ - 1);

    float inv = (float)(1.0 / pow(10000.0, (double)j / 32.0));
    float ang = (float)s * inv;
    float c = cosf(ang), sn = sinf(ang);

    long long base = (long long)row * DMODEL + hh * HD;
    float q1 = q[base + j], q2 = q[base + j + 32];
    q[base + j]      = q1 * c - q2 * sn;
    q[base + j + 32] = q2 * c + q1 * sn;
    float k1 = k[base + j], k2 = k[base + j + 32];
    k[base + j]      = k1 * c - k2 * sn;
    k[base + j + 32] = k2 * c + k1 * sn;
}

// ---------------------------------------------------------------------------
// Flash attention with WMMA tf32. 64 q-rows per block, 256 threads.
// smem: Qs,Ks,Vs,Ss,Osm,Scr [64][68] + m/l/alpha[64]
// ---------------------------------------------------------------------------
#define SLD 68
#define ATT_TILE_F (64 * SLD)
#define ATT_SMEM_BYTES ((6 * ATT_TILE_F + 192) * 4)

__global__ __launch_bounds__(256)
void attn_kernel(const float* __restrict__ q,
                 const float* __restrict__ k,
                 const float* __restrict__ v,
                 float* __restrict__ o)
{
    extern __shared__ float sm[];
    float* Qs  = sm;
    float* Ks  = Qs + ATT_TILE_F;
    float* Vs  = Ks + ATT_TILE_F;
    float* Ss  = Vs + ATT_TILE_F;
    float* Osm = Ss + ATT_TILE_F;
    float* Scr = Osm + ATT_TILE_F;
    float* m_sm = Scr + ATT_TILE_F;
    float* l_sm = m_sm + 64;
    float* a_sm = l_sm + 64;

    int qt = blockIdx.x, h = blockIdx.y, b = blockIdx.z;
    int i0 = qt * 64;
    int tid = threadIdx.x;
    int w = tid >> 5;
    long long base = ((long long)b * SEQ) * DMODEL + h * HD;

    // load Q (scaled)
#pragma unroll
    for (int t = 0; t < 4; t++) {
        int g = tid + t * 256;
        int r = g >> 4, dq = (g & 15) << 2;
        float4 val = *(const float4*)(q + base + (long long)(i0 + r) * DMODEL + dq);
        val.x *= 0.125f; val.y *= 0.125f; val.z *= 0.125f; val.w *= 0.125f;
        *(float4*)(Qs + r * SLD + dq) = val;
    }
#pragma unroll
    for (int t = 0; t < 17; t++) {
        int g = tid + t * 256;
        if (g < ATT_TILE_F) Osm[g] = 0.f;
    }
    if (tid < 64) { m_sm[tid] = -1e30f; l_sm[tid] = 0.f; }
    __syncthreads();

    int jstart = i0 - (WINDOW - 1); if (jstart < 0) jstart = 0;
    int jt0 = jstart >> 6;
    int jt1 = (i0 + 63) >> 6;

    for (int jt = jt0; jt <= jt1; jt++) {
        int j0 = jt << 6;
        // load K, V
#pragma unroll
        for (int t = 0; t < 4; t++) {
            int g = tid + t * 256;
            int jj = g >> 4, dq = (g & 15) << 2;
            long long gp = base + (long long)(j0 + jj) * DMODEL + dq;
            *(float4*)(Ks + jj * SLD + dq) = *(const float4*)(k + gp);
            *(float4*)(Vs + jj * SLD + dq) = *(const float4*)(v + gp);
        }
        __syncthreads();

        // S = Q @ K^T  (16 tiles of 16x16, 2 per warp)
#pragma unroll
        for (int tt = 0; tt < 2; tt++) {
            int tile = w + tt * 8;
            int tr = tile >> 2, tc = tile & 3;
            wmma::fragment<wmma::accumulator, 16, 16, 8, float> s_acc;
            wmma::fill_fragment(s_acc, 0.f);
#pragma unroll
            for (int ks = 0; ks < 8; ks++) {
                wmma::fragment<wmma::matrix_a, 16, 16, 8, wmma::precision::tf32, wmma::row_major> af;
                wmma::fragment<wmma::matrix_b, 16, 16, 8, wmma::precision::tf32, wmma::col_major> bf;
                wmma::load_matrix_sync(af, Qs + (tr * 16) * SLD + ks * 8, SLD);
                wmma::load_matrix_sync(bf, Ks + (tc * 16) * SLD + ks * 8, SLD);
#pragma unroll
                for (int u = 0; u < af.num_elements; u++) af.x[u] = wmma::__float_to_tf32(af.x[u]);
#pragma unroll
                for (int u = 0; u < bf.num_elements; u++) bf.x[u] = wmma::__float_to_tf32(bf.x[u]);
                wmma::mma_sync(s_acc, af, bf, s_acc);
            }
            wmma::store_matrix_sync(Ss + (tr * 16) * SLD + tc * 16, s_acc, SLD, wmma::mem_row_major);
        }
        __syncthreads();

        // softmax: 4 threads per row, 16 cols each
        {
            int r  = tid >> 2;
            int c0 = (tid & 3) << 4;
            int ii = i0 + r;
            float mx = -1e30f;
            float sv[16];
#pragma unroll
            for (int c = 0; c < 16; c++) {
                int jj = j0 + c0 + c;
                int diff = ii - jj;
                float s = Ss[r * SLD + c0 + c];
                bool valid = (diff >= 0) && (diff < WINDOW);
                sv[c] = valid ? s : -1e30f;
                if (valid) mx = fmaxf(mx, s);
            }
            mx = fmaxf(mx, __shfl_xor_sync(0xffffffffu, mx, 1));
            mx = fmaxf(mx, __shfl_xor_sync(0xffffffffu, mx, 2));
            float m_old = m_sm[r];
            float mnew = fmaxf(m_old, mx);
            float rsum = 0.f;
#pragma unroll
            for (int c = 0; c < 16; c++) {
                float p = (sv[c] > -1e29f) ? expf(sv[c] - mnew) : 0.f;
                Ss[r * SLD + c0 + c] = p;
                rsum += p;
            }
            rsum += __shfl_xor_sync(0xffffffffu, rsum, 1);
            rsum += __shfl_xor_sync(0xffffffffu, rsum, 2);
            if ((tid & 3) == 0) {
                float alpha = expf(m_old - mnew);
                m_sm[r] = mnew;
                l_sm[r] = l_sm[r] * alpha + rsum;
                a_sm[r] = alpha;
            }
        }
        __syncthreads();

        // PV = P @ V  (to scratch)
#pragma unroll
        for (int tt = 0; tt < 2; tt++) {
            int tile = w + tt * 8;
            int tr = tile >> 2, tc = tile & 3;
            wmma::fragment<wmma::accumulator, 16, 16, 8, float> o_acc;
            wmma::fill_fragment(o_acc, 0.f);
#pragma unroll
            for (int ks = 0; ks < 8; ks++) {
                wmma::fragment<wmma::matrix_a, 16, 16, 8, wmma::precision::tf32, wmma::row_major> af;
                wmma::fragment<wmma::matrix_b, 16, 16, 8, wmma::precision::tf32, wmma::row_major> bf;
                wmma::load_matrix_sync(af, Ss + (tr * 16) * SLD + ks * 8, SLD);
                wmma::load_matrix_sync(bf, Vs + (ks * 8) * SLD + tc * 16, SLD);
#pragma unroll
                for (int u = 0; u < af.num_elements; u++) af.x[u] = wmma::__float_to_tf32(af.x[u]);
#pragma unroll
                for (int u = 0; u < bf.num_elements; u++) bf.x[u] = wmma::__float_to_tf32(bf.x[u]);
                wmma::mma_sync(o_acc, af, bf, o_acc);
            }
            wmma::store_matrix_sync(Scr + (tr * 16) * SLD + tc * 16, o_acc, SLD, wmma::mem_row_major);
        }
        __syncthreads();

        // O = O*alpha + Scr
        {
            int r  = tid >> 2;
            int c0 = (tid & 3) << 4;
            float alpha = a_sm[r];
#pragma unroll
            for (int c = 0; c < 16; c++)
                Osm[r * SLD + c0 + c] = Osm[r * SLD + c0 + c] * alpha + Scr[r * SLD + c0 + c];
        }
        __syncthreads();
    }

    // write out, normalized
    {
        int r  = tid >> 2;
        int c0 = (tid & 3) << 4;
        float rl = 1.f / l_sm[r];
#pragma unroll
        for (int c = 0; c < 16; c += 4) {
            float4 val;
            val.x = Osm[r * SLD + c0 + c]     * rl;
            val.y = Osm[r * SLD + c0 + c + 1] * rl;
            val.z = Osm[r * SLD + c0 + c + 2] * rl;
            val.w = Osm[r * SLD + c0 + c + 3] * rl;
            *(float4*)(o + base + (long long)(i0 + r) * DMODEL + c0 + c) = val;
        }
    }
}

// ---------------------------------------------------------------------------
// Gating
// ---------------------------------------------------------------------------
__global__ void gate_kernel(const float* __restrict__ xn2,
                            const float* __restrict__ gw,
                            float* __restrict__ wte,
                            float* __restrict__ phis)
{
    int tok  = (blockIdx.x * blockDim.x + threadIdx.x) >> 5;
    int lane = threadIdx.x & 31;
    if (tok >= T_TOK) return;
    const float* xr = xn2 + (long long)tok * DMODEL;
    float acc[NE];
#pragma unroll
    for (int e = 0; e < NE; e++) acc[e] = 0.f;
    for (int d = lane; d < DMODEL; d += 32) {
        float xv = xr[d];
        const float* g = gw + d * NE;
#pragma unroll
        for (int e = 0; e < NE; e++) acc[e] = fmaf(xv, g[e], acc[e]);
    }
#pragma unroll
    for (int e = 0; e < NE; e++)
#pragma unroll
        for (int off = 16; off; off >>= 1)
            acc[e] += __shfl_xor_sync(0xffffffffu, acc[e], off);

    if (lane == 0) {
        float mx = acc[0];
#pragma unroll
        for (int e = 1; e < NE; e++) mx = fmaxf(mx, acc[e]);
        float p[NE], s = 0.f;
#pragma unroll
        for (int e = 0; e < NE; e++) { p[e] = expf(acc[e] - mx); s += p[e]; }
#pragma unroll
        for (int e = 0; e < NE; e++) p[e] /= s;
        int i1 = 0;
#pragma unroll
        for (int e = 1; e < NE; e++) if (p[e] > p[i1]) i1 = e;
        int i2 = -1;
#pragma unroll
        for (int e = 0; e < NE; e++)
            if (e != i1 && (i2 < 0 || p[e] > p[i2])) i2 = e;
#pragma unroll
        for (int e = 0; e < NE; e++)
            wte[(long long)tok * NE + e] = (e == i1) ? p[i1] : (e == i2) ? p[i2] : 0.f;
#pragma unroll
        for (int e = 0; e < NE; e++) atomicAdd(&phis[e], p[e]);
    }
}

// ---------------------------------------------------------------------------
// Per-expert top-CAP selection (bitonic, stable)
// ---------------------------------------------------------------------------
__global__ void expert_topk_kernel(const float* __restrict__ wte,
                                   int* __restrict__ capidx,
                                   float* __restrict__ capval)
{
    __shared__ float sv[T_TOK];
    __shared__ int   si[T_TOK];
    int e = blockIdx.x;
    for (int i = threadIdx.x; i < T_TOK; i += 1024) {
        sv[i] = wte[(long long)i * NE + e];
        si[i] = i;
    }
    __syncthreads();
    for (int kk = 2; kk <= T_TOK; kk <<= 1) {
        for (int j = kk >> 1; j > 0; j >>= 1) {
            for (int i = threadIdx.x; i < T_TOK; i += 1024) {
                int l = i ^ j;
                if (l > i) {
                    bool dir = ((i & kk) == 0);
                    float vi = sv[i], vl = sv[l];
                    int   xi = si[i], xl = si[l];
                    bool before = (vi > vl) || (vi == vl && xi < xl);
                    if (before != dir) {
                        sv[i] = vl; sv[l] = vi;
                        si[i] = xl; si[l] = xi;
                    }
                }
            }
            __syncthreads();
        }
    }
    for (int i = threadIdx.x; i < CAP; i += 1024) {
        capidx[e * CAP + i] = si[i];
        capval[e * CAP + i] = sv[i];
    }
}

// ---------------------------------------------------------------------------
// SwiGLU
// ---------------------------------------------------------------------------
__global__ void act_kernel(const float* __restrict__ hid, float* __restrict__ act)
{
    long long idx = (long long)blockIdx.x * blockDim.x + threadIdx.x;
    if (idx >= (long long)NE * CAP * DFF) return;
    int f = (int)(idx % DFF);
    long long row = idx / DFF;
    long long hbase = row * (2 * DFF);
    float h1 = hid[hbase + f];
    float h2 = hid[hbase + DFF + f];
    act[idx] = h1 * (h2 / (1.f + expf(-h2)));
}

// ---------------------------------------------------------------------------
// Utility
// ---------------------------------------------------------------------------
__global__ void zero_phis_kernel(float* __restrict__ phis)
{
    if (threadIdx.x < NE) phis[threadIdx.x] = 0.f;
}

__global__ void copy_kernel(const float* __restrict__ src, float* __restrict__ dst)
{
    long long idx = (long long)blockIdx.x * blockDim.x + threadIdx.x;
    if (idx < (long long)(OUT_MAIN / 4)) {
        ((float4*)dst)[idx] = ((const float4*)src)[idx];
    }
}

__global__ void aux_kernel(const float* __restrict__ phis, float* __restrict__ out, int out_size)
{
    if (out_size > OUT_MAIN) {
        float s = 0.f;
#pragma unroll
        for (int e = 0; e < NE; e++) {
            float pm = phis[e] / (float)T_TOK;
            s += pm * pm;
        }
        out[OUT_MAIN] = (float)NE * s;
    }
}

// ---------------------------------------------------------------------------
// Launch
// ---------------------------------------------------------------------------
extern "C" void kernel_launch(void* const* d_in, const int* in_sizes, int n_in,
                              void* d_out, int out_size)
{
    const float* x   = (const float*)d_in[0];
    const float* wq  = (const float*)d_in[1];
    const float* wk  = (const float*)d_in[2];
    const float* wv  = (const float*)d_in[3];
    const float* wo  = (const float*)d_in[4];
    const float* n1w = (const float*)d_in[5];
    const float* n2w = (const float*)d_in[6];
    const float* gw  = (const float*)d_in[7];
    const float* w1  = (const float*)d_in[8];
    const float* w2  = (const float*)d_in[9];
    float* out = (float*)d_out;

    float *xn, *qb, *kb, *vb, *ao, *hb, *xn2, *wte, *hid, *act, *capv, *phis;
    int* capi;
    cudaGetSymbolAddress((void**)&xn,  g_xn);
    cudaGetSymbolAddress((void**)&qb,  g_q);
    cudaGetSymbolAddress((void**)&kb,  g_k);
    cudaGetSymbolAddress((void**)&vb,  g_v);
    cudaGetSymbolAddress((void**)&ao,  g_ao);
    cudaGetSymbolAddress((void**)&hb,  g_h);
    cudaGetSymbolAddress((void**)&xn2, g_xn2);
    cudaGetSymbolAddress((void**)&wte, g_wte);
    cudaGetSymbolAddress((void**)&hid, g_hid);
    cudaGetSymbolAddress((void**)&act, g_act);
    cudaGetSymbolAddress((void**)&capi, g_capidx);
    cudaGetSymbolAddress((void**)&capv, g_capval);
    cudaGetSymbolAddress((void**)&phis, g_phis);

    static int attr_done = 0;
    if (!attr_done) {
        cudaFuncSetAttribute(wgemm_kernel<0>, cudaFuncAttributeMaxDynamicSharedMemorySize, GEMM_SMEM_BYTES);
        cudaFuncSetAttribute(wgemm_kernel<1>, cudaFuncAttributeMaxDynamicSharedMemorySize, GEMM_SMEM_BYTES);
        cudaFuncSetAttribute(wgemm_kernel<2>, cudaFuncAttributeMaxDynamicSharedMemorySize, GEMM_SMEM_BYTES);
        cudaFuncSetAttribute(attn_kernel, cudaFuncAttributeMaxDynamicSharedMemorySize, ATT_SMEM_BYTES);
        attr_done = 1;
    }

    // ---- sublayer 1 ----
    rmsnorm_kernel<<<T_TOK, 256>>>(x, n1w, xn);

    dim3 gProj(DMODEL / 128, T_TOK / 128, 1);  // (8, 32)
    wgemm_kernel<0><<<gProj, 256, GEMM_SMEM_BYTES>>>(xn, wq, qb, nullptr, nullptr, nullptr, nullptr,
                                                     DMODEL, DMODEL, 0, 0, 0, 0);
    wgemm_kernel<0><<<gProj, 256, GEMM_SMEM_BYTES>>>(xn, wk, kb, nullptr, nullptr, nullptr, nullptr,
                                                     DMODEL, DMODEL, 0, 0, 0, 0);
    wgemm_kernel<0><<<gProj, 256, GEMM_SMEM_BYTES>>>(xn, wv, vb, nullptr, nullptr, nullptr, nullptr,
                                                     DMODEL, DMODEL, 0, 0, 0, 0);

    rope_kernel<<<(T_TOK * NH * 32 + 255) / 256, 256>>>(qb, kb);

    attn_kernel<<<dim3(SEQ / 64, NH, NB), 256, ATT_SMEM_BYTES>>>(qb, kb, vb, ao);

    wgemm_kernel<1><<<gProj, 256, GEMM_SMEM_BYTES>>>(ao, wo, hb, x, nullptr, nullptr, nullptr,
                                                     DMODEL, DMODEL, 0, 0, 0, 0);

    // ---- sublayer 2: MoE ----
    rmsnorm_kernel<<<T_TOK, 256>>>(hb, n2w, xn2);

    zero_phis_kernel<<<1, 32>>>(phis);
    gate_kernel<<<(T_TOK * 32) / 256, 256>>>(xn2, gw, wte, phis);
    expert_topk_kernel<<<NE, 1024>>>(wte, capi, capv);

    // hidden[e] = xn2[capidx[e]] @ w1[e]
    wgemm_kernel<0><<<dim3((2 * DFF) / 128, CAP / 128, NE), 256, GEMM_SMEM_BYTES>>>(
        xn2, w1, hid, nullptr, capi, nullptr, nullptr,
        2 * DFF, DMODEL,
        0, (long long)DMODEL * 2 * DFF, (long long)CAP * 2 * DFF, CAP);

    act_kernel<<<(NE * CAP * DFF + 255) / 256, 256>>>(hid, act);

    copy_kernel<<<(OUT_MAIN / 4 + 255) / 256, 256>>>(hb, out);

    // out[capidx[e][c]] += (act[e] @ w2[e])[c] * capval[e][c]
    wgemm_kernel<2><<<dim3(DMODEL / 128, CAP / 128, NE), 256, GEMM_SMEM_BYTES>>>(
        act, w2, out, nullptr, nullptr, capi, capv,
        DMODEL, DFF,
        (long long)CAP * DFF, (long long)DFF * DMODEL, 0, CAP);

    aux_kernel<<<1, 1>>>(phis, out, out_size);

    (void)in_sizes; (void)n_in;
}

// round 5
// speedup vs baseline: 2.5803x; 1.0931x over previous
#include <cuda_runtime.h>
#include <cstdint>
#include <math.h>
#include <mma.h>

using namespace nvcuda;

// ---------------------------------------------------------------------------
// Problem constants
// ---------------------------------------------------------------------------
#define NB     2
#define SEQ    2048
#define T_TOK  4096
#define DMODEL 1024
#define NH     16
#define HD     64
#define WINDOW 1024
#define NE     8
#define DFF    2048
#define CAP    512
#define OUT_MAIN (T_TOK * DMODEL)

// ---------------------------------------------------------------------------
// Scratch
// ---------------------------------------------------------------------------
__device__ float g_xn  [T_TOK * DMODEL];
__device__ float g_q   [T_TOK * DMODEL];
__device__ float g_k   [T_TOK * DMODEL];
__device__ float g_v   [T_TOK * DMODEL];
__device__ float g_ao  [T_TOK * DMODEL];
__device__ float g_h   [T_TOK * DMODEL];
__device__ float g_xn2 [T_TOK * DMODEL];
__device__ float g_wte [T_TOK * NE];
__device__ float g_hid [NE * CAP * 2 * DFF];
__device__ float g_act [NE * CAP * DFF];
__device__ int   g_capidx[NE * CAP];
__device__ float g_capval[NE * CAP];
__device__ float g_phis[NE];

// ---------------------------------------------------------------------------
// cp.async helpers
// ---------------------------------------------------------------------------
__device__ __forceinline__ void cp16(void* dst, const void* src)
{
    unsigned int d = (unsigned int)__cvta_generic_to_shared(dst);
    asm volatile("cp.async.cg.shared.global [%0], [%1], 16;\n" :: "r"(d), "l"(src));
}
__device__ __forceinline__ void cp_commit() { asm volatile("cp.async.commit_group;\n"); }
__device__ __forceinline__ void cp_wait1()  { asm volatile("cp.async.wait_group 1;\n"); }
__device__ __forceinline__ void cp_wait0()  { asm volatile("cp.async.wait_group 0;\n"); }

// ---------------------------------------------------------------------------
// RMSNorm
// ---------------------------------------------------------------------------
__global__ void rmsnorm_kernel(const float* __restrict__ x,
                               const float* __restrict__ w,
                               float* __restrict__ o)
{
    int row = blockIdx.x;
    const float* xr = x + (long long)row * DMODEL;
    float vals[4];
    float ss = 0.f;
#pragma unroll
    for (int t = 0; t < 4; t++) {
        float v = xr[threadIdx.x + t * 256];
        vals[t] = v;
        ss += v * v;
    }
    __shared__ float red[8];
#pragma unroll
    for (int off = 16; off; off >>= 1)
        ss += __shfl_xor_sync(0xffffffffu, ss, off);
    if ((threadIdx.x & 31) == 0) red[threadIdx.x >> 5] = ss;
    __syncthreads();
    if (threadIdx.x == 0) {
        float s = 0.f;
#pragma unroll
        for (int i = 0; i < 8; i++) s += red[i];
        red[0] = s;
    }
    __syncthreads();
    float rinv = 1.f / sqrtf(red[0] / (float)DMODEL + 1e-6f);
    float* orow = o + (long long)row * DMODEL;
#pragma unroll
    for (int t = 0; t < 4; t++) {
        int d = threadIdx.x + t * 256;
        orow[d] = vals[t] * rinv * w[d];
    }
}

// ---------------------------------------------------------------------------
// WMMA tf32 GEMM (truncated tf32 -- no per-element rounding).
// Tile 128x128, BK=32, 256 threads (8 warps, each 32x64), 2 CTAs/SM.
// EPI 0: plain. EPI 1: += resid. EPI 2: scatter atomicAdd * rowScale.
// ---------------------------------------------------------------------------
#define ALD 36
#define BLD 132
#define STAGE_F (128 * ALD + 32 * BLD)     // 8832 floats
#define GEMM_SMEM_BYTES (2 * STAGE_F * 4)  // 70656

template<int EPI>
__global__ __launch_bounds__(256, 2)
void wgemm_kernel(const float* __restrict__ A,
                  const float* __restrict__ B,
                  float* __restrict__ C,
                  const float* __restrict__ resid,
                  const int*  __restrict__ rowIdxA,
                  const int*  __restrict__ outIdx,
                  const float* __restrict__ rowScale,
                  int N, int K,
                  long long aB, long long bB, long long cB, int idxB)
{
    extern __shared__ float sm[];
    __shared__ int   idx_sm[128];
    __shared__ float scl_sm[128];

    int e = blockIdx.z;
    A += (long long)e * aB;
    B += (long long)e * bB;
    C += (long long)e * cB;

    int tid = threadIdx.x;
    int w   = tid >> 5;
    int wr  = w >> 1;         // 0..3
    int wc  = w & 1;          // 0..1
    int rowBase = blockIdx.y * 128;
    int colBase = blockIdx.x * 128;

    if (tid < 128) {
        int ar = rowBase + tid;
        idx_sm[tid] = rowIdxA ? rowIdxA[e * idxB + ar] : ar;
        if (EPI == 2) {
            scl_sm[tid] = rowScale[e * idxB + ar];
            idx_sm[tid] = outIdx[e * idxB + ar];   // EPI2: scatter target rows
        }
    }
    __syncthreads();

    wmma::fragment<wmma::accumulator, 16, 16, 8, float> acc[2][4];
#pragma unroll
    for (int i = 0; i < 2; i++)
#pragma unroll
        for (int j = 0; j < 4; j++) wmma::fill_fragment(acc[i][j], 0.f);

    int nIt = K >> 5;

    auto load_tile = [&](int it, int buf) {
        float* As = sm + buf * STAGE_F;
        float* Bs = As + 128 * ALD;
        int k0 = it << 5;
#pragma unroll
        for (int t = 0; t < 4; t++) {
            int g  = tid + t * 256;
            int m  = g >> 3;
            int kq = (g & 7) << 2;
            long long arow = (EPI == 2) ? (long long)(rowBase + m) : (long long)idx_sm[m];
            cp16(As + m * ALD + kq, A + arow * K + k0 + kq);
        }
#pragma unroll
        for (int t = 0; t < 4; t++) {
            int g  = tid + t * 256;
            int kk = g >> 5;
            int nq = (g & 31) << 2;
            cp16(Bs + kk * BLD + nq, B + (long long)(k0 + kk) * N + colBase + nq);
        }
        cp_commit();
    };

    load_tile(0, 0);
    for (int it = 0; it < nIt; it++) {
        if (it + 1 < nIt) { load_tile(it + 1, (it + 1) & 1); cp_wait1(); }
        else cp_wait0();
        __syncthreads();

        float* As = sm + (it & 1) * STAGE_F;
        float* Bs = As + 128 * ALD;
#pragma unroll
        for (int ks = 0; ks < 4; ks++) {
            wmma::fragment<wmma::matrix_a, 16, 16, 8, wmma::precision::tf32, wmma::row_major> a[2];
            wmma::fragment<wmma::matrix_b, 16, 16, 8, wmma::precision::tf32, wmma::row_major> b[4];
#pragma unroll
            for (int i = 0; i < 2; i++)
                wmma::load_matrix_sync(a[i], As + (wr * 32 + i * 16) * ALD + ks * 8, ALD);
#pragma unroll
            for (int j = 0; j < 4; j++)
                wmma::load_matrix_sync(b[j], Bs + (ks * 8) * BLD + wc * 64 + j * 16, BLD);
#pragma unroll
            for (int i = 0; i < 2; i++)
#pragma unroll
                for (int j = 0; j < 4; j++)
                    wmma::mma_sync(acc[i][j], a[i], b[j], acc[i][j]);
        }
        __syncthreads();
    }

    if (EPI == 0) {
#pragma unroll
        for (int i = 0; i < 2; i++)
#pragma unroll
            for (int j = 0; j < 4; j++) {
                long long m = rowBase + wr * 32 + i * 16;
                long long n = colBase + wc * 64 + j * 16;
                wmma::store_matrix_sync(C + m * N + n, acc[i][j], N, wmma::mem_row_major);
            }
    } else {
        float* Csm = sm;   // 128 x 132
#pragma unroll
        for (int i = 0; i < 2; i++)
#pragma unroll
            for (int j = 0; j < 4; j++)
                wmma::store_matrix_sync(Csm + (wr * 32 + i * 16) * BLD + wc * 64 + j * 16,
                                        acc[i][j], BLD, wmma::mem_row_major);
        __syncthreads();
        if (EPI == 1) {
#pragma unroll
            for (int t = 0; t < 64; t++) {
                int idx = tid + t * 256;
                int m = idx >> 7, n = idx & 127;
                long long gm = (long long)(rowBase + m) * N + colBase + n;
                C[gm] = Csm[m * BLD + n] + resid[gm];
            }
        } else { // EPI 2
#pragma unroll
            for (int t = 0; t < 64; t++) {
                int idx = tid + t * 256;
                int m = idx >> 7, n = idx & 127;
                atomicAdd(&C[(long long)idx_sm[m] * N + colBase + n],
                          Csm[m * BLD + n] * scl_sm[m]);
            }
        }
    }
}

// ---------------------------------------------------------------------------
// RoPE
// ---------------------------------------------------------------------------
__global__ void rope_kernel(float* __restrict__ q, float* __restrict__ k)
{
    int idx = blockIdx.x * blockDim.x + threadIdx.x;
    if (idx >= T_TOK * NH * (HD / 2)) return;
    int j   = idx & 31;
    int hh  = (idx >> 5) & 15;
    int row = idx >> 9;
    int s   = row & (SEQ - 1);

    float inv = (float)(1.0 / pow(10000.0, (double)j / 32.0));
    float ang = (float)s * inv;
    float c = cosf(ang), sn = sinf(ang);

    long long base = (long long)row * DMODEL + hh * HD;
    float q1 = q[base + j], q2 = q[base + j + 32];
    q[base + j]      = q1 * c - q2 * sn;
    q[base + j + 32] = q2 * c + q1 * sn;
    float k1 = k[base + j], k2 = k[base + j + 32];
    k[base + j]      = k1 * c - k2 * sn;
    k[base + j + 32] = k2 * c + k1 * sn;
}

// ---------------------------------------------------------------------------
// Flash attention with WMMA tf32 (truncated). 64 q-rows per block, 256 thr.
// ---------------------------------------------------------------------------
#define SLD 68
#define ATT_TILE_F (64 * SLD)
#define ATT_SMEM_BYTES ((6 * ATT_TILE_F + 192) * 4)

__global__ __launch_bounds__(256)
void attn_kernel(const float* __restrict__ q,
                 const float* __restrict__ k,
                 const float* __restrict__ v,
                 float* __restrict__ o)
{
    extern __shared__ float sm[];
    float* Qs  = sm;
    float* Ks  = Qs + ATT_TILE_F;
    float* Vs  = Ks + ATT_TILE_F;
    float* Ss  = Vs + ATT_TILE_F;
    float* Osm = Ss + ATT_TILE_F;
    float* Scr = Osm + ATT_TILE_F;
    float* m_sm = Scr + ATT_TILE_F;
    float* l_sm = m_sm + 64;
    float* a_sm = l_sm + 64;

    int qt = blockIdx.x, h = blockIdx.y, b = blockIdx.z;
    int i0 = qt * 64;
    int tid = threadIdx.x;
    int w = tid >> 5;
    long long base = ((long long)b * SEQ) * DMODEL + h * HD;

#pragma unroll
    for (int t = 0; t < 4; t++) {
        int g = tid + t * 256;
        int r = g >> 4, dq = (g & 15) << 2;
        float4 val = *(const float4*)(q + base + (long long)(i0 + r) * DMODEL + dq);
        val.x *= 0.125f; val.y *= 0.125f; val.z *= 0.125f; val.w *= 0.125f;
        *(float4*)(Qs + r * SLD + dq) = val;
    }
#pragma unroll
    for (int t = 0; t < 17; t++) {
        int g = tid + t * 256;
        if (g < ATT_TILE_F) Osm[g] = 0.f;
    }
    if (tid < 64) { m_sm[tid] = -1e30f; l_sm[tid] = 0.f; }
    __syncthreads();

    int jstart = i0 - (WINDOW - 1); if (jstart < 0) jstart = 0;
    int jt0 = jstart >> 6;
    int jt1 = (i0 + 63) >> 6;

    for (int jt = jt0; jt <= jt1; jt++) {
        int j0 = jt << 6;
#pragma unroll
        for (int t = 0; t < 4; t++) {
            int g = tid + t * 256;
            int jj = g >> 4, dq = (g & 15) << 2;
            long long gp = base + (long long)(j0 + jj) * DMODEL + dq;
            *(float4*)(Ks + jj * SLD + dq) = *(const float4*)(k + gp);
            *(float4*)(Vs + jj * SLD + dq) = *(const float4*)(v + gp);
        }
        __syncthreads();

        // S = Q @ K^T
#pragma unroll
        for (int tt = 0; tt < 2; tt++) {
            int tile = w + tt * 8;
            int tr = tile >> 2, tc = tile & 3;
            wmma::fragment<wmma::accumulator, 16, 16, 8, float> s_acc;
            wmma::fill_fragment(s_acc, 0.f);
#pragma unroll
            for (int ks = 0; ks < 8; ks++) {
                wmma::fragment<wmma::matrix_a, 16, 16, 8, wmma::precision::tf32, wmma::row_major> af;
                wmma::fragment<wmma::matrix_b, 16, 16, 8, wmma::precision::tf32, wmma::col_major> bf;
                wmma::load_matrix_sync(af, Qs + (tr * 16) * SLD + ks * 8, SLD);
                wmma::load_matrix_sync(bf, Ks + (tc * 16) * SLD + ks * 8, SLD);
                wmma::mma_sync(s_acc, af, bf, s_acc);
            }
            wmma::store_matrix_sync(Ss + (tr * 16) * SLD + tc * 16, s_acc, SLD, wmma::mem_row_major);
        }
        __syncthreads();

        // softmax: 4 threads per row, 16 cols each
        {
            int r  = tid >> 2;
            int c0 = (tid & 3) << 4;
            int ii = i0 + r;
            float mx = -1e30f;
            float sv[16];
#pragma unroll
            for (int c = 0; c < 16; c++) {
                int jj = j0 + c0 + c;
                int diff = ii - jj;
                float s = Ss[r * SLD + c0 + c];
                bool valid = (diff >= 0) && (diff < WINDOW);
                sv[c] = valid ? s : -1e30f;
                if (valid) mx = fmaxf(mx, s);
            }
            mx = fmaxf(mx, __shfl_xor_sync(0xffffffffu, mx, 1));
            mx = fmaxf(mx, __shfl_xor_sync(0xffffffffu, mx, 2));
            float m_old = m_sm[r];
            float mnew = fmaxf(m_old, mx);
            float rsum = 0.f;
#pragma unroll
            for (int c = 0; c < 16; c++) {
                float p = (sv[c] > -1e29f) ? expf(sv[c] - mnew) : 0.f;
                Ss[r * SLD + c0 + c] = p;
                rsum += p;
            }
            rsum += __shfl_xor_sync(0xffffffffu, rsum, 1);
            rsum += __shfl_xor_sync(0xffffffffu, rsum, 2);
            if ((tid & 3) == 0) {
                float alpha = expf(m_old - mnew);
                m_sm[r] = mnew;
                l_sm[r] = l_sm[r] * alpha + rsum;
                a_sm[r] = alpha;
            }
        }
        __syncthreads();

        // PV = P @ V
#pragma unroll
        for (int tt = 0; tt < 2; tt++) {
            int tile = w + tt * 8;
            int tr = tile >> 2, tc = tile & 3;
            wmma::fragment<wmma::accumulator, 16, 16, 8, float> o_acc;
            wmma::fill_fragment(o_acc, 0.f);
#pragma unroll
            for (int ks = 0; ks < 8; ks++) {
                wmma::fragment<wmma::matrix_a, 16, 16, 8, wmma::precision::tf32, wmma::row_major> af;
                wmma::fragment<wmma::matrix_b, 16, 16, 8, wmma::precision::tf32, wmma::row_major> bf;
                wmma::load_matrix_sync(af, Ss + (tr * 16) * SLD + ks * 8, SLD);
                wmma::load_matrix_sync(bf, Vs + (ks * 8) * SLD + tc * 16, SLD);
                wmma::mma_sync(o_acc, af, bf, o_acc);
            }
            wmma::store_matrix_sync(Scr + (tr * 16) * SLD + tc * 16, o_acc, SLD, wmma::mem_row_major);
        }
        __syncthreads();

        // O = O*alpha + Scr
        {
            int r  = tid >> 2;
            int c0 = (tid & 3) << 4;
            float alpha = a_sm[r];
#pragma unroll
            for (int c = 0; c < 16; c++)
                Osm[r * SLD + c0 + c] = Osm[r * SLD + c0 + c] * alpha + Scr[r * SLD + c0 + c];
        }
        __syncthreads();
    }

    {
        int r  = tid >> 2;
        int c0 = (tid & 3) << 4;
        float rl = 1.f / l_sm[r];
#pragma unroll
        for (int c = 0; c < 16; c += 4) {
            float4 val;
            val.x = Osm[r * SLD + c0 + c]     * rl;
            val.y = Osm[r * SLD + c0 + c + 1] * rl;
            val.z = Osm[r * SLD + c0 + c + 2] * rl;
            val.w = Osm[r * SLD + c0 + c + 3] * rl;
            *(float4*)(o + base + (long long)(i0 + r) * DMODEL + c0 + c) = val;
        }
    }
}

// ---------------------------------------------------------------------------
// Gating
// ---------------------------------------------------------------------------
__global__ void gate_kernel(const float* __restrict__ xn2,
                            const float* __restrict__ gw,
                            float* __restrict__ wte,
                            float* __restrict__ phis)
{
    int tok  = (blockIdx.x * blockDim.x + threadIdx.x) >> 5;
    int lane = threadIdx.x & 31;
    if (tok >= T_TOK) return;
    const float* xr = xn2 + (long long)tok * DMODEL;
    float acc[NE];
#pragma unroll
    for (int e = 0; e < NE; e++) acc[e] = 0.f;
    for (int d = lane; d < DMODEL; d += 32) {
        float xv = xr[d];
        const float* g = gw + d * NE;
#pragma unroll
        for (int e = 0; e < NE; e++) acc[e] = fmaf(xv, g[e], acc[e]);
    }
#pragma unroll
    for (int e = 0; e < NE; e++)
#pragma unroll
        for (int off = 16; off; off >>= 1)
            acc[e] += __shfl_xor_sync(0xffffffffu, acc[e], off);

    if (lane == 0) {
        float mx = acc[0];
#pragma unroll
        for (int e = 1; e < NE; e++) mx = fmaxf(mx, acc[e]);
        float p[NE], s = 0.f;
#pragma unroll
        for (int e = 0; e < NE; e++) { p[e] = expf(acc[e] - mx); s += p[e]; }
#pragma unroll
        for (int e = 0; e < NE; e++) p[e] /= s;
        int i1 = 0;
#pragma unroll
        for (int e = 1; e < NE; e++) if (p[e] > p[i1]) i1 = e;
        int i2 = -1;
#pragma unroll
        for (int e = 0; e < NE; e++)
            if (e != i1 && (i2 < 0 || p[e] > p[i2])) i2 = e;
#pragma unroll
        for (int e = 0; e < NE; e++)
            wte[(long long)tok * NE + e] = (e == i1) ? p[i1] : (e == i2) ? p[i2] : 0.f;
#pragma unroll
        for (int e = 0; e < NE; e++) atomicAdd(&phis[e], p[e]);
    }
}

// ---------------------------------------------------------------------------
// Per-expert top-CAP selection (bitonic, stable)
// ---------------------------------------------------------------------------
__global__ void expert_topk_kernel(const float* __restrict__ wte,
                                   int* __restrict__ capidx,
                                   float* __restrict__ capval)
{
    __shared__ float sv[T_TOK];
    __shared__ int   si[T_TOK];
    int e = blockIdx.x;
    for (int i = threadIdx.x; i < T_TOK; i += 1024) {
        sv[i] = wte[(long long)i * NE + e];
        si[i] = i;
    }
    __syncthreads();
    for (int kk = 2; kk <= T_TOK; kk <<= 1) {
        for (int j = kk >> 1; j > 0; j >>= 1) {
            for (int i = threadIdx.x; i < T_TOK; i += 1024) {
                int l = i ^ j;
                if (l > i) {
                    bool dir = ((i & kk) == 0);
                    float vi = sv[i], vl = sv[l];
                    int   xi = si[i], xl = si[l];
                    bool before = (vi > vl) || (vi == vl && xi < xl);
                    if (before != dir) {
                        sv[i] = vl; sv[l] = vi;
                        si[i] = xl; si[l] = xi;
                    }
                }
            }
            __syncthreads();
        }
    }
    for (int i = threadIdx.x; i < CAP; i += 1024) {
        capidx[e * CAP + i] = si[i];
        capval[e * CAP + i] = sv[i];
    }
}

// ---------------------------------------------------------------------------
// SwiGLU
// ---------------------------------------------------------------------------
__global__ void act_kernel(const float* __restrict__ hid, float* __restrict__ act)
{
    long long idx = (long long)blockIdx.x * blockDim.x + threadIdx.x;
    if (idx >= (long long)NE * CAP * DFF) return;
    int f = (int)(idx % DFF);
    long long row = idx / DFF;
    long long hbase = row * (2 * DFF);
    float h1 = hid[hbase + f];
    float h2 = hid[hbase + DFF + f];
    act[idx] = h1 * (h2 / (1.f + expf(-h2)));
}

// ---------------------------------------------------------------------------
// Utility
// ---------------------------------------------------------------------------
__global__ void zero_phis_kernel(float* __restrict__ phis)
{
    if (threadIdx.x < NE) phis[threadIdx.x] = 0.f;
}

__global__ void copy_kernel(const float* __restrict__ src, float* __restrict__ dst)
{
    long long idx = (long long)blockIdx.x * blockDim.x + threadIdx.x;
    if (idx < (long long)(OUT_MAIN / 4)) {
        ((float4*)dst)[idx] = ((const float4*)src)[idx];
    }
}

__global__ void aux_kernel(const float* __restrict__ phis, float* __restrict__ out, int out_size)
{
    if (out_size > OUT_MAIN) {
        float s = 0.f;
#pragma unroll
        for (int e = 0; e < NE; e++) {
            float pm = phis[e] / (float)T_TOK;
            s += pm * pm;
        }
        out[OUT_MAIN] = (float)NE * s;
    }
}

// ---------------------------------------------------------------------------
// Launch
// ---------------------------------------------------------------------------
extern "C" void kernel_launch(void* const* d_in, const int* in_sizes, int n_in,
                              void* d_out, int out_size)
{
    const float* x   = (const float*)d_in[0];
    const float* wq  = (const float*)d_in[1];
    const float* wk  = (const float*)d_in[2];
    const float* wv  = (const float*)d_in[3];
    const float* wo  = (const float*)d_in[4];
    const float* n1w = (const float*)d_in[5];
    const float* n2w = (const float*)d_in[6];
    const float* gw  = (const float*)d_in[7];
    const float* w1  = (const float*)d_in[8];
    const float* w2  = (const float*)d_in[9];
    float* out = (float*)d_out;

    float *xn, *qb, *kb, *vb, *ao, *hb, *xn2, *wte, *hid, *act, *capv, *phis;
    int* capi;
    cudaGetSymbolAddress((void**)&xn,  g_xn);
    cudaGetSymbolAddress((void**)&qb,  g_q);
    cudaGetSymbolAddress((void**)&kb,  g_k);
    cudaGetSymbolAddress((void**)&vb,  g_v);
    cudaGetSymbolAddress((void**)&ao,  g_ao);
    cudaGetSymbolAddress((void**)&hb,  g_h);
    cudaGetSymbolAddress((void**)&xn2, g_xn2);
    cudaGetSymbolAddress((void**)&wte, g_wte);
    cudaGetSymbolAddress((void**)&hid, g_hid);
    cudaGetSymbolAddress((void**)&act, g_act);
    cudaGetSymbolAddress((void**)&capi, g_capidx);
    cudaGetSymbolAddress((void**)&capv, g_capval);
    cudaGetSymbolAddress((void**)&phis, g_phis);

    static int attr_done = 0;
    if (!attr_done) {
        cudaFuncSetAttribute(wgemm_kernel<0>, cudaFuncAttributeMaxDynamicSharedMemorySize, GEMM_SMEM_BYTES);
        cudaFuncSetAttribute(wgemm_kernel<1>, cudaFuncAttributeMaxDynamicSharedMemorySize, GEMM_SMEM_BYTES);
        cudaFuncSetAttribute(wgemm_kernel<2>, cudaFuncAttributeMaxDynamicSharedMemorySize, GEMM_SMEM_BYTES);
        cudaFuncSetAttribute(attn_kernel, cudaFuncAttributeMaxDynamicSharedMemorySize, ATT_SMEM_BYTES);
        attr_done = 1;
    }

    // ---- sublayer 1 ----
    rmsnorm_kernel<<<T_TOK, 256>>>(x, n1w, xn);

    dim3 gProj(DMODEL / 128, T_TOK / 128, 1);  // (8, 32)
    wgemm_kernel<0><<<gProj, 256, GEMM_SMEM_BYTES>>>(xn, wq, qb, nullptr, nullptr, nullptr, nullptr,
                                                     DMODEL, DMODEL, 0, 0, 0, 0);
    wgemm_kernel<0><<<gProj, 256, GEMM_SMEM_BYTES>>>(xn, wk, kb, nullptr, nullptr, nullptr, nullptr,
                                                     DMODEL, DMODEL, 0, 0, 0, 0);
    wgemm_kernel<0><<<gProj, 256, GEMM_SMEM_BYTES>>>(xn, wv, vb, nullptr, nullptr, nullptr, nullptr,
                                                     DMODEL, DMODEL, 0, 0, 0, 0);

    rope_kernel<<<(T_TOK * NH * 32 + 255) / 256, 256>>>(qb, kb);

    attn_kernel<<<dim3(SEQ / 64, NH, NB), 256, ATT_SMEM_BYTES>>>(qb, kb, vb, ao);

    wgemm_kernel<1><<<gProj, 256, GEMM_SMEM_BYTES>>>(ao, wo, hb, x, nullptr, nullptr, nullptr,
                                                     DMODEL, DMODEL, 0, 0, 0, 0);

    // ---- sublayer 2: MoE ----
    rmsnorm_kernel<<<T_TOK, 256>>>(hb, n2w, xn2);

    zero_phis_kernel<<<1, 32>>>(phis);
    gate_kernel<<<(T_TOK * 32) / 256, 256>>>(xn2, gw, wte, phis);
    expert_topk_kernel<<<NE, 1024>>>(wte, capi, capv);

    // hidden[e] = xn2[capidx[e]] @ w1[e]
    wgemm_kernel<0><<<dim3((2 * DFF) / 128, CAP / 128, NE), 256, GEMM_SMEM_BYTES>>>(
        xn2, w1, hid, nullptr, capi, nullptr, nullptr,
        2 * DFF, DMODEL,
        0, (long long)DMODEL * 2 * DFF, (long long)CAP * 2 * DFF, CAP);

    act_kernel<<<(NE * CAP * DFF + 255) / 256, 256>>>(hid, act);

    copy_kernel<<<(OUT_MAIN / 4 + 255) / 256, 256>>>(hb, out);

    // out[capidx[e][c]] += (act[e] @ w2[e])[c] * capval[e][c]
    wgemm_kernel<2><<<dim3(DMODEL / 128, CAP / 128, NE), 256, GEMM_SMEM_BYTES>>>(
        act, w2, out, nullptr, nullptr, capi, capv,
        DMODEL, DFF,
        (long long)CAP * DFF, (long long)DFF * DMODEL, 0, CAP);

    aux_kernel<<<1, 1>>>(phis, out, out_size);

    (void)in_sizes; (void)n_in;
}

// round 6
// speedup vs baseline: 2.6265x; 1.0179x over previous
#include <cuda_runtime.h>
#include <cstdint>
#include <math.h>
#include <mma.h>

using namespace nvcuda;

// ---------------------------------------------------------------------------
// Problem constants
// ---------------------------------------------------------------------------
#define NB     2
#define SEQ    2048
#define T_TOK  4096
#define DMODEL 1024
#define NH     16
#define HD     64
#define WINDOW 1024
#define NE     8
#define DFF    2048
#define CAP    512
#define OUT_MAIN (T_TOK * DMODEL)

// ---------------------------------------------------------------------------
// Scratch
// ---------------------------------------------------------------------------
__device__ float g_xn  [T_TOK * DMODEL];
__device__ float g_q   [T_TOK * DMODEL];
__device__ float g_k   [T_TOK * DMODEL];
__device__ float g_v   [T_TOK * DMODEL];
__device__ float g_ao  [T_TOK * DMODEL];
__device__ float g_h   [T_TOK * DMODEL];
__device__ float g_xn2 [T_TOK * DMODEL];
__device__ float g_wte [T_TOK * NE];
__device__ float g_hid [NE * CAP * 2 * DFF];
__device__ float g_act [NE * CAP * DFF];
__device__ int   g_capidx[NE * CAP];
__device__ float g_capval[NE * CAP];
__device__ float g_phis[NE];

// ---------------------------------------------------------------------------
// cp.async helpers
// ---------------------------------------------------------------------------
__device__ __forceinline__ void cp16(void* dst, const void* src)
{
    unsigned int d = (unsigned int)__cvta_generic_to_shared(dst);
    asm volatile("cp.async.cg.shared.global [%0], [%1], 16;\n" :: "r"(d), "l"(src));
}
__device__ __forceinline__ void cp_commit() { asm volatile("cp.async.commit_group;\n"); }
__device__ __forceinline__ void cp_wait1()  { asm volatile("cp.async.wait_group 1;\n"); }
__device__ __forceinline__ void cp_wait0()  { asm volatile("cp.async.wait_group 0;\n"); }

// ---------------------------------------------------------------------------
// RMSNorm
// ---------------------------------------------------------------------------
__global__ void rmsnorm_kernel(const float* __restrict__ x,
                               const float* __restrict__ w,
                               float* __restrict__ o)
{
    int row = blockIdx.x;
    const float* xr = x + (long long)row * DMODEL;
    float vals[4];
    float ss = 0.f;
#pragma unroll
    for (int t = 0; t < 4; t++) {
        float v = xr[threadIdx.x + t * 256];
        vals[t] = v;
        ss += v * v;
    }
    __shared__ float red[8];
#pragma unroll
    for (int off = 16; off; off >>= 1)
        ss += __shfl_xor_sync(0xffffffffu, ss, off);
    if ((threadIdx.x & 31) == 0) red[threadIdx.x >> 5] = ss;
    __syncthreads();
    if (threadIdx.x == 0) {
        float s = 0.f;
#pragma unroll
        for (int i = 0; i < 8; i++) s += red[i];
        red[0] = s;
    }
    __syncthreads();
    float rinv = 1.f / sqrtf(red[0] / (float)DMODEL + 1e-6f);
    float* orow = o + (long long)row * DMODEL;
#pragma unroll
    for (int t = 0; t < 4; t++) {
        int d = threadIdx.x + t * 256;
        orow[d] = vals[t] * rinv * w[d];
    }
}

// ---------------------------------------------------------------------------
// WMMA tf32 GEMM (truncated tf32).
// CTA tile 256x128, BK=32, 256 threads, 8 warps each 64x64 (4x2 warp grid).
// EPI 0: plain. EPI 1: += resid. EPI 2: scatter atomicAdd * rowScale.
// EPI 3: fused QKV (B/C selected by blockIdx.x>>3).
// ---------------------------------------------------------------------------
#define BM 256
#define BN 128
#define ALD 36
#define BLD 132
#define STAGE_F (BM * ALD + 32 * BLD)      // 13440 floats
#define GEMM_SMEM_BYTES (2 * STAGE_F * 4)  // 107520 B

template<int EPI>
__global__ __launch_bounds__(256)
void wgemm_kernel(const float* __restrict__ A,
                  const float* __restrict__ B0,
                  const float* __restrict__ B1,
                  const float* __restrict__ B2,
                  float* __restrict__ C0,
                  float* __restrict__ C1,
                  float* __restrict__ C2,
                  const float* __restrict__ resid,
                  const int*  __restrict__ rowIdxA,
                  const int*  __restrict__ outIdx,
                  const float* __restrict__ rowScale,
                  int N, int K,
                  long long aB, long long bB, long long cB, int idxB)
{
    extern __shared__ float sm[];
    __shared__ int   idx_sm[BM];
    __shared__ float scl_sm[BM];

    int e = blockIdx.z;
    const float* A_ = A + (long long)e * aB;
    const float* B_;
    float* C_;
    int colBase;
    if (EPI == 3) {
        int sel = blockIdx.x >> 3;
        colBase = (blockIdx.x & 7) * BN;
        B_ = (sel == 0) ? B0 : (sel == 1) ? B1 : B2;
        C_ = (sel == 0) ? C0 : (sel == 1) ? C1 : C2;
    } else {
        colBase = blockIdx.x * BN;
        B_ = B0 + (long long)e * bB;
        C_ = C0 + (long long)e * cB;
    }

    int tid = threadIdx.x;
    int w   = tid >> 5;
    int wr  = w >> 1;         // 0..3  (64-row band)
    int wc  = w & 1;          // 0..1  (64-col band)
    int rowBase = blockIdx.y * BM;

    {
        int ar = rowBase + tid;
        idx_sm[tid] = (EPI == 0 && rowIdxA) ? rowIdxA[e * idxB + ar] : ar;
        if (EPI == 2) {
            scl_sm[tid] = rowScale[e * idxB + ar];
            idx_sm[tid] = outIdx[e * idxB + ar];   // scatter target rows
        }
    }
    __syncthreads();

    wmma::fragment<wmma::accumulator, 16, 16, 8, float> acc[4][4];
#pragma unroll
    for (int i = 0; i < 4; i++)
#pragma unroll
        for (int j = 0; j < 4; j++) wmma::fill_fragment(acc[i][j], 0.f);

    int nIt = K >> 5;

    auto load_tile = [&](int it, int buf) {
        float* As = sm + buf * STAGE_F;
        float* Bs = As + BM * ALD;
        int k0 = it << 5;
#pragma unroll
        for (int t = 0; t < 8; t++) {
            int g  = tid + t * 256;
            int m  = g >> 3;
            int kq = (g & 7) << 2;
            long long arow = (EPI == 2) ? (long long)(rowBase + m) : (long long)idx_sm[m];
            cp16(As + m * ALD + kq, A_ + arow * K + k0 + kq);
        }
#pragma unroll
        for (int t = 0; t < 4; t++) {
            int g  = tid + t * 256;
            int kk = g >> 5;
            int nq = (g & 31) << 2;
            cp16(Bs + kk * BLD + nq, B_ + (long long)(k0 + kk) * N + colBase + nq);
        }
        cp_commit();
    };

    load_tile(0, 0);
    for (int it = 0; it < nIt; it++) {
        if (it + 1 < nIt) { load_tile(it + 1, (it + 1) & 1); cp_wait1(); }
        else cp_wait0();
        __syncthreads();

        float* As = sm + (it & 1) * STAGE_F;
        float* Bs = As + BM * ALD;
#pragma unroll
        for (int ks = 0; ks < 4; ks++) {
            wmma::fragment<wmma::matrix_a, 16, 16, 8, wmma::precision::tf32, wmma::row_major> a[4];
            wmma::fragment<wmma::matrix_b, 16, 16, 8, wmma::precision::tf32, wmma::row_major> b[4];
#pragma unroll
            for (int i = 0; i < 4; i++)
                wmma::load_matrix_sync(a[i], As + (wr * 64 + i * 16) * ALD + ks * 8, ALD);
#pragma unroll
            for (int j = 0; j < 4; j++)
                wmma::load_matrix_sync(b[j], Bs + (ks * 8) * BLD + wc * 64 + j * 16, BLD);
#pragma unroll
            for (int i = 0; i < 4; i++)
#pragma unroll
                for (int j = 0; j < 4; j++)
                    wmma::mma_sync(acc[i][j], a[i], b[j], acc[i][j]);
        }
        __syncthreads();
    }

    if (EPI == 0 || EPI == 3) {
#pragma unroll
        for (int i = 0; i < 4; i++)
#pragma unroll
            for (int j = 0; j < 4; j++) {
                long long m = rowBase + wr * 64 + i * 16;
                long long n = colBase + wc * 64 + j * 16;
                wmma::store_matrix_sync(C_ + m * N + n, acc[i][j], N, wmma::mem_row_major);
            }
    } else {
        float* Csm = sm;   // 128 x 132 staging, two halves
#pragma unroll
        for (int half = 0; half < 2; half++) {
            if ((wr >> 1) == half) {
#pragma unroll
                for (int i = 0; i < 4; i++)
#pragma unroll
                    for (int j = 0; j < 4; j++)
                        wmma::store_matrix_sync(Csm + ((wr & 1) * 64 + i * 16) * BLD + wc * 64 + j * 16,
                                                acc[i][j], BLD, wmma::mem_row_major);
            }
            __syncthreads();
#pragma unroll
            for (int t = 0; t < 64; t++) {
                int idx = tid + t * 256;
                int m = idx >> 7, n = idx & 127;
                int gmRow = rowBase + half * 128 + m;
                if (EPI == 1) {
                    long long gm = (long long)gmRow * N + colBase + n;
                    C_[gm] = Csm[m * BLD + n] + resid[gm];
                } else { // EPI 2
                    atomicAdd(&C_[(long long)idx_sm[half * 128 + m] * N + colBase + n],
                              Csm[m * BLD + n] * scl_sm[half * 128 + m]);
                }
            }
            __syncthreads();
        }
    }
}

// ---------------------------------------------------------------------------
// RoPE
// ---------------------------------------------------------------------------
__global__ void rope_kernel(float* __restrict__ q, float* __restrict__ k)
{
    int idx = blockIdx.x * blockDim.x + threadIdx.x;
    if (idx >= T_TOK * NH * (HD / 2)) return;
    int j   = idx & 31;
    int hh  = (idx >> 5) & 15;
    int row = idx >> 9;
    int s   = row & (SEQ - 1);

    float inv = (float)(1.0 / pow(10000.0, (double)j / 32.0));
    float ang = (float)s * inv;
    float c = cosf(ang), sn = sinf(ang);

    long long base = (long long)row * DMODEL + hh * HD;
    float q1 = q[base + j], q2 = q[base + j + 32];
    q[base + j]      = q1 * c - q2 * sn;
    q[base + j + 32] = q2 * c + q1 * sn;
    float k1 = k[base + j], k2 = k[base + j + 32];
    k[base + j]      = k1 * c - k2 * sn;
    k[base + j + 32] = k2 * c + k1 * sn;
}

// ---------------------------------------------------------------------------
// Flash attention with WMMA tf32 (truncated). 64 q-rows per block, 256 thr,
// 2 CTAs/SM.
// ---------------------------------------------------------------------------
#define SLD 68
#define ATT_TILE_F (64 * SLD)
#define ATT_SMEM_BYTES ((6 * ATT_TILE_F + 192) * 4)

__global__ __launch_bounds__(256, 2)
void attn_kernel(const float* __restrict__ q,
                 const float* __restrict__ k,
                 const float* __restrict__ v,
                 float* __restrict__ o)
{
    extern __shared__ float sm[];
    float* Qs  = sm;
    float* Ks  = Qs + ATT_TILE_F;
    float* Vs  = Ks + ATT_TILE_F;
    float* Ss  = Vs + ATT_TILE_F;
    float* Osm = Ss + ATT_TILE_F;
    float* Scr = Osm + ATT_TILE_F;
    float* m_sm = Scr + ATT_TILE_F;
    float* l_sm = m_sm + 64;
    float* a_sm = l_sm + 64;

    int qt = blockIdx.x, h = blockIdx.y, b = blockIdx.z;
    int i0 = qt * 64;
    int tid = threadIdx.x;
    int w = tid >> 5;
    long long base = ((long long)b * SEQ) * DMODEL + h * HD;

#pragma unroll
    for (int t = 0; t < 4; t++) {
        int g = tid + t * 256;
        int r = g >> 4, dq = (g & 15) << 2;
        float4 val = *(const float4*)(q + base + (long long)(i0 + r) * DMODEL + dq);
        val.x *= 0.125f; val.y *= 0.125f; val.z *= 0.125f; val.w *= 0.125f;
        *(float4*)(Qs + r * SLD + dq) = val;
    }
#pragma unroll
    for (int t = 0; t < 17; t++) {
        int g = tid + t * 256;
        if (g < ATT_TILE_F) Osm[g] = 0.f;
    }
    if (tid < 64) { m_sm[tid] = -1e30f; l_sm[tid] = 0.f; }
    __syncthreads();

    int jstart = i0 - (WINDOW - 1); if (jstart < 0) jstart = 0;
    int jt0 = jstart >> 6;
    int jt1 = (i0 + 63) >> 6;

    for (int jt = jt0; jt <= jt1; jt++) {
        int j0 = jt << 6;
#pragma unroll
        for (int t = 0; t < 4; t++) {
            int g = tid + t * 256;
            int jj = g >> 4, dq = (g & 15) << 2;
            long long gp = base + (long long)(j0 + jj) * DMODEL + dq;
            *(float4*)(Ks + jj * SLD + dq) = *(const float4*)(k + gp);
            *(float4*)(Vs + jj * SLD + dq) = *(const float4*)(v + gp);
        }
        __syncthreads();

        // S = Q @ K^T
#pragma unroll
        for (int tt = 0; tt < 2; tt++) {
            int tile = w + tt * 8;
            int tr = tile >> 2, tc = tile & 3;
            wmma::fragment<wmma::accumulator, 16, 16, 8, float> s_acc;
            wmma::fill_fragment(s_acc, 0.f);
#pragma unroll
            for (int ks = 0; ks < 8; ks++) {
                wmma::fragment<wmma::matrix_a, 16, 16, 8, wmma::precision::tf32, wmma::row_major> af;
                wmma::fragment<wmma::matrix_b, 16, 16, 8, wmma::precision::tf32, wmma::col_major> bf;
                wmma::load_matrix_sync(af, Qs + (tr * 16) * SLD + ks * 8, SLD);
                wmma::load_matrix_sync(bf, Ks + (tc * 16) * SLD + ks * 8, SLD);
                wmma::mma_sync(s_acc, af, bf, s_acc);
            }
            wmma::store_matrix_sync(Ss + (tr * 16) * SLD + tc * 16, s_acc, SLD, wmma::mem_row_major);
        }
        __syncthreads();

        // softmax: 4 threads per row, 16 cols each
        {
            int r  = tid >> 2;
            int c0 = (tid & 3) << 4;
            int ii = i0 + r;
            float mx = -1e30f;
            float sv[16];
#pragma unroll
            for (int c = 0; c < 16; c++) {
                int jj = j0 + c0 + c;
                int diff = ii - jj;
                float s = Ss[r * SLD + c0 + c];
                bool valid = (diff >= 0) && (diff < WINDOW);
                sv[c] = valid ? s : -1e30f;
                if (valid) mx = fmaxf(mx, s);
            }
            mx = fmaxf(mx, __shfl_xor_sync(0xffffffffu, mx, 1));
            mx = fmaxf(mx, __shfl_xor_sync(0xffffffffu, mx, 2));
            float m_old = m_sm[r];
            float mnew = fmaxf(m_old, mx);
            float rsum = 0.f;
#pragma unroll
            for (int c = 0; c < 16; c++) {
                float p = (sv[c] > -1e29f) ? expf(sv[c] - mnew) : 0.f;
                Ss[r * SLD + c0 + c] = p;
                rsum += p;
            }
            rsum += __shfl_xor_sync(0xffffffffu, rsum, 1);
            rsum += __shfl_xor_sync(0xffffffffu, rsum, 2);
            if ((tid & 3) == 0) {
                float alpha = expf(m_old - mnew);
                m_sm[r] = mnew;
                l_sm[r] = l_sm[r] * alpha + rsum;
                a_sm[r] = alpha;
            }
        }
        __syncthreads();

        // PV = P @ V
#pragma unroll
        for (int tt = 0; tt < 2; tt++) {
            int tile = w + tt * 8;
            int tr = tile >> 2, tc = tile & 3;
            wmma::fragment<wmma::accumulator, 16, 16, 8, float> o_acc;
            wmma::fill_fragment(o_acc, 0.f);
#pragma unroll
            for (int ks = 0; ks < 8; ks++) {
                wmma::fragment<wmma::matrix_a, 16, 16, 8, wmma::precision::tf32, wmma::row_major> af;
                wmma::fragment<wmma::matrix_b, 16, 16, 8, wmma::precision::tf32, wmma::row_major> bf;
                wmma::load_matrix_sync(af, Ss + (tr * 16) * SLD + ks * 8, SLD);
                wmma::load_matrix_sync(bf, Vs + (ks * 8) * SLD + tc * 16, SLD);
                wmma::mma_sync(o_acc, af, bf, o_acc);
            }
            wmma::store_matrix_sync(Scr + (tr * 16) * SLD + tc * 16, o_acc, SLD, wmma::mem_row_major);
        }
        __syncthreads();

        // O = O*alpha + Scr
        {
            int r  = tid >> 2;
            int c0 = (tid & 3) << 4;
            float alpha = a_sm[r];
#pragma unroll
            for (int c = 0; c < 16; c++)
                Osm[r * SLD + c0 + c] = Osm[r * SLD + c0 + c] * alpha + Scr[r * SLD + c0 + c];
        }
        __syncthreads();
    }

    {
        int r  = tid >> 2;
        int c0 = (tid & 3) << 4;
        float rl = 1.f / l_sm[r];
#pragma unroll
        for (int c = 0; c < 16; c += 4) {
            float4 val;
            val.x = Osm[r * SLD + c0 + c]     * rl;
            val.y = Osm[r * SLD + c0 + c + 1] * rl;
            val.z = Osm[r * SLD + c0 + c + 2] * rl;
            val.w = Osm[r * SLD + c0 + c + 3] * rl;
            *(float4*)(o + base + (long long)(i0 + r) * DMODEL + c0 + c) = val;
        }
    }
}

// ---------------------------------------------------------------------------
// Gating
// ---------------------------------------------------------------------------
__global__ void gate_kernel(const float* __restrict__ xn2,
                            const float* __restrict__ gw,
                            float* __restrict__ wte,
                            float* __restrict__ phis)
{
    int tok  = (blockIdx.x * blockDim.x + threadIdx.x) >> 5;
    int lane = threadIdx.x & 31;
    if (tok >= T_TOK) return;
    const float* xr = xn2 + (long long)tok * DMODEL;
    float acc[NE];
#pragma unroll
    for (int e = 0; e < NE; e++) acc[e] = 0.f;
    for (int d = lane; d < DMODEL; d += 32) {
        float xv = xr[d];
        const float* g = gw + d * NE;
#pragma unroll
        for (int e = 0; e < NE; e++) acc[e] = fmaf(xv, g[e], acc[e]);
    }
#pragma unroll
    for (int e = 0; e < NE; e++)
#pragma unroll
        for (int off = 16; off; off >>= 1)
            acc[e] += __shfl_xor_sync(0xffffffffu, acc[e], off);

    if (lane == 0) {
        float mx = acc[0];
#pragma unroll
        for (int e = 1; e < NE; e++) mx = fmaxf(mx, acc[e]);
        float p[NE], s = 0.f;
#pragma unroll
        for (int e = 0; e < NE; e++) { p[e] = expf(acc[e] - mx); s += p[e]; }
#pragma unroll
        for (int e = 0; e < NE; e++) p[e] /= s;
        int i1 = 0;
#pragma unroll
        for (int e = 1; e < NE; e++) if (p[e] > p[i1]) i1 = e;
        int i2 = -1;
#pragma unroll
        for (int e = 0; e < NE; e++)
            if (e != i1 && (i2 < 0 || p[e] > p[i2])) i2 = e;
#pragma unroll
        for (int e = 0; e < NE; e++)
            wte[(long long)tok * NE + e] = (e == i1) ? p[i1] : (e == i2) ? p[i2] : 0.f;
#pragma unroll
        for (int e = 0; e < NE; e++) atomicAdd(&phis[e], p[e]);
    }
}

// ---------------------------------------------------------------------------
// Per-expert top-CAP selection (bitonic, stable)
// ---------------------------------------------------------------------------
__global__ void expert_topk_kernel(const float* __restrict__ wte,
                                   int* __restrict__ capidx,
                                   float* __restrict__ capval)
{
    __shared__ float sv[T_TOK];
    __shared__ int   si[T_TOK];
    int e = blockIdx.x;
    for (int i = threadIdx.x; i < T_TOK; i += 1024) {
        sv[i] = wte[(long long)i * NE + e];
        si[i] = i;
    }
    __syncthreads();
    for (int kk = 2; kk <= T_TOK; kk <<= 1) {
        for (int j = kk >> 1; j > 0; j >>= 1) {
            for (int i = threadIdx.x; i < T_TOK; i += 1024) {
                int l = i ^ j;
                if (l > i) {
                    bool dir = ((i & kk) == 0);
                    float vi = sv[i], vl = sv[l];
                    int   xi = si[i], xl = si[l];
                    bool before = (vi > vl) || (vi == vl && xi < xl);
                    if (before != dir) {
                        sv[i] = vl; sv[l] = vi;
                        si[i] = xl; si[l] = xi;
                    }
                }
            }
            __syncthreads();
        }
    }
    for (int i = threadIdx.x; i < CAP; i += 1024) {
        capidx[e * CAP + i] = si[i];
        capval[e * CAP + i] = sv[i];
    }
}

// ---------------------------------------------------------------------------
// SwiGLU
// ---------------------------------------------------------------------------
__global__ void act_kernel(const float* __restrict__ hid, float* __restrict__ act)
{
    long long idx = (long long)blockIdx.x * blockDim.x + threadIdx.x;
    if (idx >= (long long)NE * CAP * DFF) return;
    int f = (int)(idx % DFF);
    long long row = idx / DFF;
    long long hbase = row * (2 * DFF);
    float h1 = hid[hbase + f];
    float h2 = hid[hbase + DFF + f];
    act[idx] = h1 * (h2 / (1.f + expf(-h2)));
}

// ---------------------------------------------------------------------------
// Utility
// ---------------------------------------------------------------------------
__global__ void zero_phis_kernel(float* __restrict__ phis)
{
    if (threadIdx.x < NE) phis[threadIdx.x] = 0.f;
}

__global__ void copy_kernel(const float* __restrict__ src, float* __restrict__ dst)
{
    long long idx = (long long)blockIdx.x * blockDim.x + threadIdx.x;
    if (idx < (long long)(OUT_MAIN / 4)) {
        ((float4*)dst)[idx] = ((const float4*)src)[idx];
    }
}

__global__ void aux_kernel(const float* __restrict__ phis, float* __restrict__ out, int out_size)
{
    if (out_size > OUT_MAIN) {
        float s = 0.f;
#pragma unroll
        for (int e = 0; e < NE; e++) {
            float pm = phis[e] / (float)T_TOK;
            s += pm * pm;
        }
        out[OUT_MAIN] = (float)NE * s;
    }
}

// ---------------------------------------------------------------------------
// Launch
// ---------------------------------------------------------------------------
extern "C" void kernel_launch(void* const* d_in, const int* in_sizes, int n_in,
                              void* d_out, int out_size)
{
    const float* x   = (const float*)d_in[0];
    const float* wq  = (const float*)d_in[1];
    const float* wk  = (const float*)d_in[2];
    const float* wv  = (const float*)d_in[3];
    const float* wo  = (const float*)d_in[4];
    const float* n1w = (const float*)d_in[5];
    const float* n2w = (const float*)d_in[6];
    const float* gw  = (const float*)d_in[7];
    const float* w1  = (const float*)d_in[8];
    const float* w2  = (const float*)d_in[9];
    float* out = (float*)d_out;

    float *xn, *qb, *kb, *vb, *ao, *hb, *xn2, *wte, *hid, *act, *capv, *phis;
    int* capi;
    cudaGetSymbolAddress((void**)&xn,  g_xn);
    cudaGetSymbolAddress((void**)&qb,  g_q);
    cudaGetSymbolAddress((void**)&kb,  g_k);
    cudaGetSymbolAddress((void**)&vb,  g_v);
    cudaGetSymbolAddress((void**)&ao,  g_ao);
    cudaGetSymbolAddress((void**)&hb,  g_h);
    cudaGetSymbolAddress((void**)&xn2, g_xn2);
    cudaGetSymbolAddress((void**)&wte, g_wte);
    cudaGetSymbolAddress((void**)&hid, g_hid);
    cudaGetSymbolAddress((void**)&act, g_act);
    cudaGetSymbolAddress((void**)&capi, g_capidx);
    cudaGetSymbolAddress((void**)&capv, g_capval);
    cudaGetSymbolAddress((void**)&phis, g_phis);

    static int attr_done = 0;
    if (!attr_done) {
        cudaFuncSetAttribute(wgemm_kernel<0>, cudaFuncAttributeMaxDynamicSharedMemorySize, GEMM_SMEM_BYTES);
        cudaFuncSetAttribute(wgemm_kernel<1>, cudaFuncAttributeMaxDynamicSharedMemorySize, GEMM_SMEM_BYTES);
        cudaFuncSetAttribute(wgemm_kernel<2>, cudaFuncAttributeMaxDynamicSharedMemorySize, GEMM_SMEM_BYTES);
        cudaFuncSetAttribute(wgemm_kernel<3>, cudaFuncAttributeMaxDynamicSharedMemorySize, GEMM_SMEM_BYTES);
        cudaFuncSetAttribute(attn_kernel, cudaFuncAttributeMaxDynamicSharedMemorySize, ATT_SMEM_BYTES);
        attr_done = 1;
    }

    // ---- sublayer 1 ----
    rmsnorm_kernel<<<T_TOK, 256>>>(x, n1w, xn);

    // Fused QKV: grid.x = 3 weights x 8 col-blocks, grid.y = 4096/256
    wgemm_kernel<3><<<dim3(24, T_TOK / BM, 1), 256, GEMM_SMEM_BYTES>>>(
        xn, wq, wk, wv, qb, kb, vb, nullptr, nullptr, nullptr, nullptr,
        DMODEL, DMODEL, 0, 0, 0, 0);

    rope_kernel<<<(T_TOK * NH * 32 + 255) / 256, 256>>>(qb, kb);

    attn_kernel<<<dim3(SEQ / 64, NH, NB), 256, ATT_SMEM_BYTES>>>(qb, kb, vb, ao);

    wgemm_kernel<1><<<dim3(DMODEL / BN, T_TOK / BM, 1), 256, GEMM_SMEM_BYTES>>>(
        ao, wo, nullptr, nullptr, hb, nullptr, nullptr, x, nullptr, nullptr, nullptr,
        DMODEL, DMODEL, 0, 0, 0, 0);

    // ---- sublayer 2: MoE ----
    rmsnorm_kernel<<<T_TOK, 256>>>(hb, n2w, xn2);

    zero_phis_kernel<<<1, 32>>>(phis);
    gate_kernel<<<(T_TOK * 32) / 256, 256>>>(xn2, gw, wte, phis);
    expert_topk_kernel<<<NE, 1024>>>(wte, capi, capv);

    // hidden[e] = xn2[capidx[e]] @ w1[e]   (M=512, N=4096, K=1024)
    wgemm_kernel<0><<<dim3((2 * DFF) / BN, CAP / BM, NE), 256, GEMM_SMEM_BYTES>>>(
        xn2, w1, nullptr, nullptr, hid, nullptr, nullptr, nullptr, capi, nullptr, nullptr,
        2 * DFF, DMODEL,
        0, (long long)DMODEL * 2 * DFF, (long long)CAP * 2 * DFF, CAP);

    act_kernel<<<(NE * CAP * DFF + 255) / 256, 256>>>(hid, act);

    copy_kernel<<<(OUT_MAIN / 4 + 255) / 256, 256>>>(hb, out);

    // out[capidx[e][c]] += (act[e] @ w2[e])[c] * capval[e][c]  (M=512,N=1024,K=2048)
    wgemm_kernel<2><<<dim3(DMODEL / BN, CAP / BM, NE), 256, GEMM_SMEM_BYTES>>>(
        act, w2, nullptr, nullptr, out, nullptr, nullptr, nullptr, nullptr, capi, capv,
        DMODEL, DFF,
        (long long)CAP * DFF, (long long)DFF * DMODEL, 0, CAP);

    aux_kernel<<<1, 1>>>(phis, out, out_size);

    (void)in_sizes; (void)n_in;
}